// round 2
// baseline (speedup 1.0000x reference)
#include <cuda_runtime.h>
#include <cuda_bf16.h>

// Problem constants (LinkPredictorGAT): N_NODES=100000, D=256, E=1000000, H=128
// Inputs (metadata order): z[f32, N*D], edge_label_index[int32!, 2*E]  (JAX x64 is
// disabled -> int64 request silently becomes int32; stub dtype legend has no i64),
// W1[f32, 512*128], b1[f32,128], W2[f32,128], b2[f32,1]
// Output: out[f32, E]
//
// Strategy: out_e = relu(z[src]@W1[:256] + z[dst]@W1[256:] + b1) @ W2 + b2
//   Stage 1: UV[n, 0:128]  = z[n] @ W1[0:256]    (u)
//            UV[n, 128:256]= z[n] @ W1[256:512]  (v)
//   Stage 2: warp-per-edge: h = relu(u[src]+v[dst]+b1); out = h . W2 + b2

#define MAX_NODES 100000
#define DD 256          // D
#define HH 128          // H

// scratch: 100000 * 256 floats = 102.4 MB (static device global, allowed)
__device__ float g_UV[(size_t)MAX_NODES * 2 * HH];

// ---------------- Stage 1: tiled fp32 GEMM ----------------
#define BM 128
#define BN 128
#define BK 16
#define TM 8
#define TN 8

__global__ __launch_bounds__(256, 2)
void uv_gemm_kernel(const float* __restrict__ Z,
                    const float* __restrict__ W1,
                    float* __restrict__ UV,
                    int M) {
    __shared__ float As[BK][BM];   // A transposed: As[k][m]
    __shared__ float Bs[BK][BN];   // Bs[k][n]

    const int sl = blockIdx.y;                    // 0: u-slice, 1: v-slice
    const float* W = W1 + (size_t)sl * 256 * HH;  // W1 rows [sl*256, sl*256+256)
    const int row0 = blockIdx.x * BM;
    const int colOff = sl * HH;

    const int tid = threadIdx.x;
    const int tx = tid & 15;   // 16 thread-cols * TN(8) = 128
    const int ty = tid >> 4;   // 16 thread-rows * TM(8) = 128

    float acc[TM][TN];
#pragma unroll
    for (int i = 0; i < TM; i++)
#pragma unroll
        for (int j = 0; j < TN; j++) acc[i][j] = 0.f;

    for (int k0 = 0; k0 < DD; k0 += BK) {
        // Load A tile: 512 float4s over 256 threads (2 each)
#pragma unroll
        for (int it = 0; it < 2; ++it) {
            int idx = tid + it * 256;      // 0..511
            int r   = idx >> 2;            // 0..127
            int kq  = (idx & 3) * 4;       // 0,4,8,12
            float4 vz = make_float4(0.f, 0.f, 0.f, 0.f);
            if (row0 + r < M)
                vz = *reinterpret_cast<const float4*>(&Z[(size_t)(row0 + r) * DD + k0 + kq]);
            As[kq + 0][r] = vz.x;
            As[kq + 1][r] = vz.y;
            As[kq + 2][r] = vz.z;
            As[kq + 3][r] = vz.w;
        }
        // Load B tile: 512 float4s over 256 threads (2 each)
#pragma unroll
        for (int it = 0; it < 2; ++it) {
            int idx = tid + it * 256;      // 0..511
            int kk  = idx >> 5;            // 0..15
            int n   = (idx & 31) * 4;      // 0..124
            float4 vw = *reinterpret_cast<const float4*>(&W[(size_t)(k0 + kk) * HH + n]);
            *reinterpret_cast<float4*>(&Bs[kk][n]) = vw;
        }
        __syncthreads();

#pragma unroll
        for (int k = 0; k < BK; k++) {
            float a[TM], b[TN];
            float4 a0 = *reinterpret_cast<const float4*>(&As[k][ty * TM + 0]);
            float4 a1 = *reinterpret_cast<const float4*>(&As[k][ty * TM + 4]);
            a[0]=a0.x; a[1]=a0.y; a[2]=a0.z; a[3]=a0.w;
            a[4]=a1.x; a[5]=a1.y; a[6]=a1.z; a[7]=a1.w;
            float4 b0 = *reinterpret_cast<const float4*>(&Bs[k][tx * TN + 0]);
            float4 b1v = *reinterpret_cast<const float4*>(&Bs[k][tx * TN + 4]);
            b[0]=b0.x; b[1]=b0.y; b[2]=b0.z; b[3]=b0.w;
            b[4]=b1v.x; b[5]=b1v.y; b[6]=b1v.z; b[7]=b1v.w;
#pragma unroll
            for (int i = 0; i < TM; i++)
#pragma unroll
                for (int j = 0; j < TN; j++)
                    acc[i][j] = fmaf(a[i], b[j], acc[i][j]);
        }
        __syncthreads();
    }

#pragma unroll
    for (int i = 0; i < TM; i++) {
        int r = row0 + ty * TM + i;
        if (r < M) {
            float* dst = &UV[(size_t)r * (2 * HH) + colOff + tx * TN];
            *reinterpret_cast<float4*>(dst + 0) =
                make_float4(acc[i][0], acc[i][1], acc[i][2], acc[i][3]);
            *reinterpret_cast<float4*>(dst + 4) =
                make_float4(acc[i][4], acc[i][5], acc[i][6], acc[i][7]);
        }
    }
}

// ---------------- Stage 2: warp-per-edge gather + relu + dot ----------------
__global__ __launch_bounds__(256)
void edge_kernel(const int* __restrict__ eli,
                 const float* __restrict__ UV,
                 const float* __restrict__ b1,
                 const float* __restrict__ W2,
                 const float* __restrict__ b2,
                 float* __restrict__ out,
                 int E) {
    int gwarp = (blockIdx.x * blockDim.x + threadIdx.x) >> 5;
    int lane  = threadIdx.x & 31;
    if (gwarp >= E) return;

    int s = __ldg(&eli[gwarp]);
    int d = __ldg(&eli[(size_t)E + gwarp]);

    const float4* up = reinterpret_cast<const float4*>(UV + (size_t)s * (2 * HH));
    const float4* vp = reinterpret_cast<const float4*>(UV + (size_t)d * (2 * HH) + HH);

    float4 u  = __ldg(up + lane);
    float4 v  = __ldg(vp + lane);
    float4 bb = __ldg(reinterpret_cast<const float4*>(b1) + lane);
    float4 w  = __ldg(reinterpret_cast<const float4*>(W2) + lane);

    float hx = fmaxf(u.x + v.x + bb.x, 0.f);
    float hy = fmaxf(u.y + v.y + bb.y, 0.f);
    float hz = fmaxf(u.z + v.z + bb.z, 0.f);
    float hw = fmaxf(u.w + v.w + bb.w, 0.f);

    float p = hx * w.x + hy * w.y + hz * w.z + hw * w.w;
#pragma unroll
    for (int o = 16; o > 0; o >>= 1)
        p += __shfl_down_sync(0xffffffffu, p, o);

    if (lane == 0) out[gwarp] = p + __ldg(b2);
}

extern "C" void kernel_launch(void* const* d_in, const int* in_sizes, int n_in,
                              void* d_out, int out_size) {
    const float* z   = (const float*)d_in[0];
    const int*   eli = (const int*)d_in[1];
    const float* W1  = (const float*)d_in[2];
    const float* b1  = (const float*)d_in[3];
    const float* W2  = (const float*)d_in[4];
    const float* b2  = (const float*)d_in[5];
    float*       out = (float*)d_out;

    const int M = in_sizes[0] / DD;   // number of nodes
    const int E = out_size;           // number of edges

    float* UV = nullptr;
    cudaGetSymbolAddress((void**)&UV, g_UV);

    dim3 ggrid((M + BM - 1) / BM, 2);
    uv_gemm_kernel<<<ggrid, 256>>>(z, W1, UV, M);

    int warpsPerBlock = 256 / 32;
    int nblk = (E + warpsPerBlock - 1) / warpsPerBlock;
    edge_kernel<<<nblk, 256>>>(eli, UV, b1, W2, b2, out, E);
}

// round 3
// speedup vs baseline: 1.0396x; 1.0396x over previous
#include <cuda_runtime.h>
#include <cuda_bf16.h>

// LinkPredictorGAT: N_NODES=100000, D=256, E=1000000, H=128
// Inputs: z[f32 N*D], edge_label_index[i32 2*E], W1[f32 512*128], b1[f32 128],
//         W2[f32 128], b2[f32 1].  Output: out[f32 E]
//
// out_e = relu(z[src]@W1[:256] + z[dst]@W1[256:] + b1) @ W2 + b2
//   Stage 1 (GEMM, packed f32x2 FFMA): UV[n,0:128]=z[n]@W1a + b1 (b1 folded),
//                                      UV[n,128:256]=z[n]@W1b
//   Stage 2: 2 edges per warp: h=relu(u[src]+v[dst]); out = h.W2 + b2

#define MAX_NODES 100000
#define DD 256
#define HH 128

__device__ float g_UV[(size_t)MAX_NODES * 2 * HH];

// ---------------- Stage 1: tiled fp32 GEMM with fma.rn.f32x2 ----------------
#define BM 128
#define BN 128
#define BK 16
#define TM 8
#define TN 8

__global__ __launch_bounds__(256, 2)
void uv_gemm_kernel(const float* __restrict__ Z,
                    const float* __restrict__ W1,
                    const float* __restrict__ b1,
                    float* __restrict__ UV,
                    int M) {
    // A stored duplicated: As2[k][2m] = As2[k][2m+1] = Z[row0+m][k0+k]
    __shared__ float As2[BK][BM * 2];   // 16 KB
    __shared__ float Bs[BK][BN];        // 8 KB

    const int sl = blockIdx.y;                    // 0: u-slice (+b1), 1: v-slice
    const float* W = W1 + (size_t)sl * 256 * HH;
    const int row0 = blockIdx.x * BM;
    const int colOff = sl * HH;

    const int tid = threadIdx.x;
    const int tx = tid & 15;   // 16 * TN(8) = 128 cols
    const int ty = tid >> 4;   // 16 * TM(8) = 128 rows

    // packed f32x2 accumulators: acc2[i][p] holds cols {2p, 2p+1}
    unsigned long long acc2[TM][TN / 2];
#pragma unroll
    for (int i = 0; i < TM; i++)
#pragma unroll
        for (int p = 0; p < TN / 2; p++) acc2[i][p] = 0ull;  // {0f,0f}

    for (int k0 = 0; k0 < DD; k0 += BK) {
        // Load A tile: 512 float4s over 256 threads (2 each), duplicated store
#pragma unroll
        for (int it = 0; it < 2; ++it) {
            int idx = tid + it * 256;      // 0..511
            int r   = idx >> 2;            // 0..127
            int kq  = (idx & 3) * 4;       // 0,4,8,12
            float4 vz = make_float4(0.f, 0.f, 0.f, 0.f);
            if (row0 + r < M)
                vz = *reinterpret_cast<const float4*>(&Z[(size_t)(row0 + r) * DD + k0 + kq]);
            As2[kq + 0][2 * r] = vz.x;  As2[kq + 0][2 * r + 1] = vz.x;
            As2[kq + 1][2 * r] = vz.y;  As2[kq + 1][2 * r + 1] = vz.y;
            As2[kq + 2][2 * r] = vz.z;  As2[kq + 2][2 * r + 1] = vz.z;
            As2[kq + 3][2 * r] = vz.w;  As2[kq + 3][2 * r + 1] = vz.w;
        }
        // Load B tile
#pragma unroll
        for (int it = 0; it < 2; ++it) {
            int idx = tid + it * 256;
            int kk  = idx >> 5;            // 0..15
            int n   = (idx & 31) * 4;      // 0..124
            *reinterpret_cast<float4*>(&Bs[kk][n]) =
                *reinterpret_cast<const float4*>(&W[(size_t)(k0 + kk) * HH + n]);
        }
        __syncthreads();

#pragma unroll
        for (int k = 0; k < BK; k++) {
            // a duplicated pairs: {a_i, a_i}
            unsigned long long a2[TM];
            const unsigned long long* ap =
                reinterpret_cast<const unsigned long long*>(&As2[k][ty * TM * 2]);
#pragma unroll
            for (int i = 0; i < TM; i++) a2[i] = ap[i];
            // b natural pairs: {b_2p, b_2p+1}
            unsigned long long b2r[TN / 2];
            const unsigned long long* bp =
                reinterpret_cast<const unsigned long long*>(&Bs[k][tx * TN]);
#pragma unroll
            for (int p = 0; p < TN / 2; p++) b2r[p] = bp[p];

#pragma unroll
            for (int i = 0; i < TM; i++)
#pragma unroll
                for (int p = 0; p < TN / 2; p++)
                    asm("fma.rn.f32x2 %0, %1, %2, %0;"
                        : "+l"(acc2[i][p])
                        : "l"(a2[i]), "l"(b2r[p]));
        }
        __syncthreads();
    }

    // epilogue: fold b1 into u-slice
    float bias[TN];
#pragma unroll
    for (int j = 0; j < TN; j++)
        bias[j] = (sl == 0) ? __ldg(&b1[tx * TN + j]) : 0.f;

#pragma unroll
    for (int i = 0; i < TM; i++) {
        int r = row0 + ty * TM + i;
        if (r < M) {
            float c[TN];
#pragma unroll
            for (int p = 0; p < TN / 2; p++) {
                float2 f = *reinterpret_cast<float2*>(&acc2[i][p]);
                c[2 * p]     = f.x + bias[2 * p];
                c[2 * p + 1] = f.y + bias[2 * p + 1];
            }
            float* dst = &UV[(size_t)r * (2 * HH) + colOff + tx * TN];
            *reinterpret_cast<float4*>(dst + 0) = make_float4(c[0], c[1], c[2], c[3]);
            *reinterpret_cast<float4*>(dst + 4) = make_float4(c[4], c[5], c[6], c[7]);
        }
    }
}

// ---------------- Stage 2: 2 edges per warp ----------------
__global__ __launch_bounds__(256)
void edge_kernel(const int* __restrict__ eli,
                 const float* __restrict__ UV,
                 const float* __restrict__ W2,
                 const float* __restrict__ b2,
                 float* __restrict__ out,
                 int E) {
    int gwarp = (blockIdx.x * blockDim.x + threadIdx.x) >> 5;
    int lane  = threadIdx.x & 31;
    int e0 = gwarp * 2;
    if (e0 >= E) return;
    bool has1 = (e0 + 1) < E;

    int s0 = __ldg(&eli[e0]);
    int d0 = __ldg(&eli[(size_t)E + e0]);
    int s1 = has1 ? __ldg(&eli[e0 + 1]) : s0;
    int d1 = has1 ? __ldg(&eli[(size_t)E + e0 + 1]) : d0;

    const float4* u0p = reinterpret_cast<const float4*>(UV + (size_t)s0 * (2 * HH));
    const float4* v0p = reinterpret_cast<const float4*>(UV + (size_t)d0 * (2 * HH) + HH);
    const float4* u1p = reinterpret_cast<const float4*>(UV + (size_t)s1 * (2 * HH));
    const float4* v1p = reinterpret_cast<const float4*>(UV + (size_t)d1 * (2 * HH) + HH);

    float4 u0 = __ldg(u0p + lane);
    float4 v0 = __ldg(v0p + lane);
    float4 u1 = __ldg(u1p + lane);
    float4 v1 = __ldg(v1p + lane);
    float4 w  = __ldg(reinterpret_cast<const float4*>(W2) + lane);

    float p0 = fmaxf(u0.x + v0.x, 0.f) * w.x + fmaxf(u0.y + v0.y, 0.f) * w.y
             + fmaxf(u0.z + v0.z, 0.f) * w.z + fmaxf(u0.w + v0.w, 0.f) * w.w;
    float p1 = fmaxf(u1.x + v1.x, 0.f) * w.x + fmaxf(u1.y + v1.y, 0.f) * w.y
             + fmaxf(u1.z + v1.z, 0.f) * w.z + fmaxf(u1.w + v1.w, 0.f) * w.w;

#pragma unroll
    for (int o = 16; o > 0; o >>= 1) {
        p0 += __shfl_down_sync(0xffffffffu, p0, o);
        p1 += __shfl_down_sync(0xffffffffu, p1, o);
    }

    if (lane == 0) {
        float bb = __ldg(b2);
        out[e0] = p0 + bb;
        if (has1) out[e0 + 1] = p1 + bb;
    }
}

extern "C" void kernel_launch(void* const* d_in, const int* in_sizes, int n_in,
                              void* d_out, int out_size) {
    const float* z   = (const float*)d_in[0];
    const int*   eli = (const int*)d_in[1];
    const float* W1  = (const float*)d_in[2];
    const float* b1  = (const float*)d_in[3];
    const float* W2  = (const float*)d_in[4];
    const float* b2  = (const float*)d_in[5];
    float*       out = (float*)d_out;

    const int M = in_sizes[0] / DD;
    const int E = out_size;

    float* UV = nullptr;
    cudaGetSymbolAddress((void**)&UV, g_UV);

    dim3 ggrid((M + BM - 1) / BM, 2);
    uv_gemm_kernel<<<ggrid, 256>>>(z, W1, b1, UV, M);

    int pairs = (E + 1) / 2;                       // 2 edges per warp
    int warpsPerBlock = 256 / 32;
    int nblk = (pairs + warpsPerBlock - 1) / warpsPerBlock;
    edge_kernel<<<nblk, 256>>>(eli, UV, W2, b2, out, E);
}

// round 5
// speedup vs baseline: 2.2962x; 2.2087x over previous
#include <cuda_runtime.h>
#include <cuda_bf16.h>
#include <cstdint>

// LinkPredictorGAT: N_NODES=100000, D=256, E=1000000, H=128
// out_e = relu(z[src]@W1[:256] + z[dst]@W1[256:] + b1) @ W2 + b2
//
// Stage 0: split Z -> Zh,Zl (bf16 hi/lo); W1 -> WhT,WlT ([N=256,K=256] K-major)
// Stage 1: mma.sync bf16 HMMA GEMM with split compensation:
//          UV[M,256] = Zh@Wh + Zh@Wl + Zl@Wh (fp32 accum), +b1 on cols 0..127
// Stage 2: 4 edges/warp: out = relu(u[src]+v[dst]) . W2 + b2

#define MAX_NODES 100000
#define DD 256
#define HH 128

__device__ float         g_UV [(size_t)MAX_NODES * 2 * HH];     // 102.4 MB
__device__ __nv_bfloat16 g_Zh [(size_t)MAX_NODES * DD];          // 51.2 MB
__device__ __nv_bfloat16 g_Zl [(size_t)MAX_NODES * DD];          // 51.2 MB
__device__ __nv_bfloat16 g_WhT[256 * 256];
__device__ __nv_bfloat16 g_WlT[256 * 256];

__device__ __forceinline__ uint32_t smem_u32(const void* p) {
    uint32_t a;
    asm("{ .reg .u64 t; cvta.to.shared.u64 t, %1; cvt.u32.u64 %0, t; }" : "=r"(a) : "l"(p));
    return a;
}

#define CP_ASYNC16(dst, src) \
    asm volatile("cp.async.cg.shared.global [%0], [%1], 16;" :: "r"(dst), "l"(src) : "memory")
#define CP_COMMIT() asm volatile("cp.async.commit_group;" ::: "memory")
#define CP_WAIT_1()  asm volatile("cp.async.wait_group 1;" ::: "memory")
#define CP_WAIT_0()  asm volatile("cp.async.wait_group 0;" ::: "memory")

#define LDMATRIX_X4(r0, r1, r2, r3, addr) \
    asm volatile("ldmatrix.sync.aligned.m8n8.x4.shared.b16 {%0,%1,%2,%3}, [%4];" \
                 : "=r"(r0), "=r"(r1), "=r"(r2), "=r"(r3) : "r"(addr))

#define MMA_BF16(d, a0, a1, a2, a3, b0, b1) \
    asm volatile("mma.sync.aligned.m16n8k16.row.col.f32.bf16.bf16.f32 " \
                 "{%0,%1,%2,%3}, {%4,%5,%6,%7}, {%8,%9}, {%0,%1,%2,%3};" \
                 : "+f"((d)[0]), "+f"((d)[1]), "+f"((d)[2]), "+f"((d)[3]) \
                 : "r"(a0), "r"(a1), "r"(a2), "r"(a3), "r"(b0), "r"(b1))

// ---------------- Stage 0a: split Z into bf16 hi/lo ----------------
__global__ __launch_bounds__(256)
void split_z_kernel(const float* __restrict__ Z,
                    __nv_bfloat16* __restrict__ Zh,
                    __nv_bfloat16* __restrict__ Zl,
                    int n4) {
    int i = blockIdx.x * blockDim.x + threadIdx.x;
    if (i >= n4) return;
    float4 z4 = reinterpret_cast<const float4*>(Z)[i];
    __nv_bfloat16 hx = __float2bfloat16_rn(z4.x);
    __nv_bfloat16 hy = __float2bfloat16_rn(z4.y);
    __nv_bfloat16 hz = __float2bfloat16_rn(z4.z);
    __nv_bfloat16 hw = __float2bfloat16_rn(z4.w);
    __nv_bfloat16 lx = __float2bfloat16_rn(z4.x - __bfloat162float(hx));
    __nv_bfloat16 ly = __float2bfloat16_rn(z4.y - __bfloat162float(hy));
    __nv_bfloat16 lz = __float2bfloat16_rn(z4.z - __bfloat162float(hz));
    __nv_bfloat16 lw = __float2bfloat16_rn(z4.w - __bfloat162float(hw));
    __nv_bfloat162* Zh2 = reinterpret_cast<__nv_bfloat162*>(Zh);
    __nv_bfloat162* Zl2 = reinterpret_cast<__nv_bfloat162*>(Zl);
    Zh2[2 * i]     = __nv_bfloat162(hx, hy);
    Zh2[2 * i + 1] = __nv_bfloat162(hz, hw);
    Zl2[2 * i]     = __nv_bfloat162(lx, ly);
    Zl2[2 * i + 1] = __nv_bfloat162(lz, lw);
}

// ---------------- Stage 0b: build transposed split W ----------------
__global__ __launch_bounds__(256)
void split_w_kernel(const float* __restrict__ W1,
                    __nv_bfloat16* __restrict__ WhT,
                    __nv_bfloat16* __restrict__ WlT) {
    int idx = blockIdx.x * blockDim.x + threadIdx.x;
    if (idx >= 256 * 256) return;
    int n = idx & 255;
    int k = idx >> 8;
    float val = (n < HH) ? W1[(size_t)k * HH + n]
                         : W1[(size_t)(256 + k) * HH + (n - HH)];
    __nv_bfloat16 h = __float2bfloat16_rn(val);
    __nv_bfloat16 l = __float2bfloat16_rn(val - __bfloat162float(h));
    WhT[(size_t)n * 256 + k] = h;
    WlT[(size_t)n * 256 + k] = l;
}

// ---------------- Stage 1: bf16 HMMA GEMM (mma.sync) ----------------
// SMEM: A stages at 0 / 16K, B stages at 32K / 48K. 128B rows, SW128 swizzle.
#define GSM_TOTAL 65536

__global__ __launch_bounds__(256, 2)
void uv_gemm_mma_kernel(const __nv_bfloat16* __restrict__ Zh,
                        const __nv_bfloat16* __restrict__ Zl,
                        const __nv_bfloat16* __restrict__ WhT,
                        const __nv_bfloat16* __restrict__ WlT,
                        const float* __restrict__ b1,
                        float* __restrict__ UV,
                        int M) {
    extern __shared__ char smem[];
    const uint32_t sbase = smem_u32(smem);
    const int tid  = threadIdx.x;
    const int wid  = tid >> 5;
    const int lane = tid & 31;
    const int wm   = wid & 3;          // warp row group: 32 rows each
    const int wn   = wid >> 2;         // warp col group: 64 cols each
    const int row0 = blockIdx.x * 128;
    const int byn  = blockIdx.y * 128; // block col offset in [0,256)

    // cp.async load lane decomposition (per thread, 4 iters x (A+B))
    // idx = tid + i*256 -> r = idx>>3 (0..127), u = idx&7 (16B unit)
    // ldmatrix lane decomposition
    const int g  = lane >> 3;          // 0..3
    const int lr = lane & 7;
    const int uAbit = g >> 1;          // A: k-half bit
    const int uBbit = g & 1;           // B: k-half bit
    // A row for m-tile mi: wm*32 + mi*16 + (g&1)*8 + lr
    int rA0 = wm * 32 + (g & 1) * 8 + lr;        // mi=0
    // B n-row for pair np: wn*64 + np*16 + (g>>1)*8 + lr
    int nB0 = wn * 64 + (g >> 1) * 8 + lr;       // np=0

    float acc[2][8][4];
#pragma unroll
    for (int mi = 0; mi < 2; mi++)
#pragma unroll
        for (int ni = 0; ni < 8; ni++)
#pragma unroll
            for (int q = 0; q < 4; q++) acc[mi][ni][q] = 0.f;

    // ---- load issue helper (macro-ish lambda) ----
    auto issue_loads = [&](int c) {
        const __nv_bfloat16* Asrc = (c >= 8) ? Zl : Zh;
        const __nv_bfloat16* Bsrc = (c >= 4 && c < 8) ? WlT : WhT;
        const int kc = (c & 3) * 64;
        const int s  = c & 1;
        const uint32_t aBase = sbase + s * 16384;
        const uint32_t bBase = sbase + 32768 + s * 16384;
#pragma unroll
        for (int i = 0; i < 4; ++i) {
            int idx = tid + i * 256;
            int r = idx >> 3;
            int u = idx & 7;
            uint32_t soff = (uint32_t)(r * 128 + ((u ^ (r & 7)) << 4));
            int gr = row0 + r; if (gr > M - 1) gr = M - 1;
            const __nv_bfloat16* gA = Asrc + (size_t)gr * 256 + kc + u * 8;
            CP_ASYNC16(aBase + soff, gA);
            const __nv_bfloat16* gB = Bsrc + (size_t)(byn + r) * 256 + kc + u * 8;
            CP_ASYNC16(bBase + soff, gB);
        }
        CP_COMMIT();
    };

    issue_loads(0);

    for (int c = 0; c < 12; ++c) {
        if (c < 11) { issue_loads(c + 1); CP_WAIT_1(); }
        else        { CP_WAIT_0(); }
        __syncthreads();

        const int s = c & 1;
        const uint32_t aBase = sbase + s * 16384;
        const uint32_t bBase = sbase + 32768 + s * 16384;

#pragma unroll
        for (int kk = 0; kk < 4; ++kk) {
            // A fragments: 2 m-tiles
            uint32_t af[2][4];
#pragma unroll
            for (int mi = 0; mi < 2; ++mi) {
                int r = rA0 + mi * 16;
                uint32_t addr = aBase + (uint32_t)(r * 128 +
                                (((kk * 2 + uAbit) ^ lr) << 4));
                LDMATRIX_X4(af[mi][0], af[mi][1], af[mi][2], af[mi][3], addr);
            }
            // B fragments: 8 n-tiles via 4 x4-loads
            uint32_t bf[8][2];
#pragma unroll
            for (int np = 0; np < 4; ++np) {
                int n = nB0 + np * 16;
                uint32_t addr = bBase + (uint32_t)(n * 128 +
                                (((kk * 2 + uBbit) ^ lr) << 4));
                uint32_t q0, q1, q2, q3;
                LDMATRIX_X4(q0, q1, q2, q3, addr);
                bf[np * 2][0] = q0; bf[np * 2][1] = q1;
                bf[np * 2 + 1][0] = q2; bf[np * 2 + 1][1] = q3;
            }
#pragma unroll
            for (int mi = 0; mi < 2; ++mi)
#pragma unroll
                for (int ni = 0; ni < 8; ++ni)
                    MMA_BF16(acc[mi][ni], af[mi][0], af[mi][1], af[mi][2], af[mi][3],
                             bf[ni][0], bf[ni][1]);
        }
        __syncthreads();
    }

    // ---- epilogue: add b1 (block by==0 covers cols 0..127), store fp32 ----
    const int trow  = lane >> 2;
    const int tcol2 = (lane & 3) * 2;
    float2 bias[8];
#pragma unroll
    for (int ni = 0; ni < 8; ++ni) {
        if (blockIdx.y == 0) {
            int col = wn * 64 + ni * 8 + tcol2;
            bias[ni] = make_float2(__ldg(&b1[col]), __ldg(&b1[col + 1]));
        } else {
            bias[ni] = make_float2(0.f, 0.f);
        }
    }
#pragma unroll
    for (int mi = 0; mi < 2; ++mi) {
        int rbase = row0 + wm * 32 + mi * 16 + trow;
#pragma unroll
        for (int h = 0; h < 2; ++h) {
            int r = rbase + h * 8;
            if (r < M) {
                float* dst = &UV[(size_t)r * 256 + byn + wn * 64 + tcol2];
#pragma unroll
                for (int ni = 0; ni < 8; ++ni) {
                    float2 v = make_float2(acc[mi][ni][h * 2] + bias[ni].x,
                                           acc[mi][ni][h * 2 + 1] + bias[ni].y);
                    *reinterpret_cast<float2*>(dst + ni * 8) = v;
                }
            }
        }
    }
}

// ---------------- Stage 2: 4 edges per warp ----------------
__global__ __launch_bounds__(256)
void edge_kernel(const int* __restrict__ eli,
                 const float* __restrict__ UV,
                 const float* __restrict__ W2,
                 const float* __restrict__ b2,
                 float* __restrict__ out,
                 int E) {
    int gwarp = (blockIdx.x * blockDim.x + threadIdx.x) >> 5;
    int lane  = threadIdx.x & 31;
    int e0 = gwarp * 4;
    if (e0 >= E) return;

    float4 w = __ldg(reinterpret_cast<const float4*>(W2) + lane);

    int s[4], d[4];
#pragma unroll
    for (int i = 0; i < 4; ++i) {
        int e = min(e0 + i, E - 1);
        s[i] = __ldg(&eli[e]);
        d[i] = __ldg(&eli[(size_t)E + e]);
    }
    float4 u[4], v[4];
#pragma unroll
    for (int i = 0; i < 4; ++i) {
        u[i] = __ldg(reinterpret_cast<const float4*>(UV + (size_t)s[i] * 256) + lane);
        v[i] = __ldg(reinterpret_cast<const float4*>(UV + (size_t)d[i] * 256 + HH) + lane);
    }
    float p[4];
#pragma unroll
    for (int i = 0; i < 4; ++i) {
        p[i] = fmaxf(u[i].x + v[i].x, 0.f) * w.x + fmaxf(u[i].y + v[i].y, 0.f) * w.y
             + fmaxf(u[i].z + v[i].z, 0.f) * w.z + fmaxf(u[i].w + v[i].w, 0.f) * w.w;
    }
#pragma unroll
    for (int o = 16; o > 0; o >>= 1) {
#pragma unroll
        for (int i = 0; i < 4; ++i)
            p[i] += __shfl_down_sync(0xffffffffu, p[i], o);
    }
    if (lane == 0) {
        float bb = __ldg(b2);
#pragma unroll
        for (int i = 0; i < 4; ++i)
            if (e0 + i < E) out[e0 + i] = p[i] + bb;
    }
}

extern "C" void kernel_launch(void* const* d_in, const int* in_sizes, int n_in,
                              void* d_out, int out_size) {
    const float* z   = (const float*)d_in[0];
    const int*   eli = (const int*)d_in[1];
    const float* W1  = (const float*)d_in[2];
    const float* b1  = (const float*)d_in[3];
    const float* W2  = (const float*)d_in[4];
    const float* b2  = (const float*)d_in[5];
    float*       out = (float*)d_out;

    const int M = in_sizes[0] / DD;
    const int E = out_size;

    float *UV; __nv_bfloat16 *Zh, *Zl, *WhT, *WlT;
    cudaGetSymbolAddress((void**)&UV,  g_UV);
    cudaGetSymbolAddress((void**)&Zh,  g_Zh);
    cudaGetSymbolAddress((void**)&Zl,  g_Zl);
    cudaGetSymbolAddress((void**)&WhT, g_WhT);
    cudaGetSymbolAddress((void**)&WlT, g_WlT);

    cudaFuncSetAttribute(uv_gemm_mma_kernel,
                         cudaFuncAttributeMaxDynamicSharedMemorySize, GSM_TOTAL);

    int n4 = M * DD / 4;
    split_z_kernel<<<(n4 + 255) / 256, 256>>>(z, Zh, Zl, n4);
    split_w_kernel<<<(256 * 256 + 255) / 256, 256>>>(W1, WhT, WlT);

    dim3 ggrid((M + 127) / 128, 2);
    uv_gemm_mma_kernel<<<ggrid, 256, GSM_TOTAL>>>(Zh, Zl, WhT, WlT, b1, UV, M);

    int quads = (E + 3) / 4;
    int warpsPerBlock = 256 / 32;
    int nblk = (quads + warpsPerBlock - 1) / warpsPerBlock;
    edge_kernel<<<nblk, 256>>>(eli, UV, W2, b2, out, E);
}

// round 6
// speedup vs baseline: 2.3842x; 1.0383x over previous
#include <cuda_runtime.h>
#include <cuda_bf16.h>
#include <cuda_fp16.h>
#include <cstdint>

// LinkPredictorGAT: N_NODES=100000, D=256, E=1000000, H=128
// out_e = relu(z[src]@W1[:256] + z[dst]@W1[256:] + b1) @ W2 + b2
//
// Stage 0: W1 -> WhT,WlT bf16 hi/lo, transposed to [N=256,K=256] K-major.
// Stage 1: fused GEMM: load Z fp32 tiles, split to bf16 hi/lo in-kernel,
//          UV[M,256](fp16) = Zh@Wh + Zh@Wl + Zl@Wh (+b1 on cols<128), mma.sync bf16.
// Stage 2: 4 edges/warp on fp16 UV: out = relu(u[src]+v[dst]) . W2 + b2

#define MAX_NODES 100000
#define DD 256
#define HH 128

__device__ __half        g_UV [(size_t)MAX_NODES * 2 * HH];     // 51.2 MB
__device__ __nv_bfloat16 g_WhT[256 * 256];
__device__ __nv_bfloat16 g_WlT[256 * 256];

__device__ __forceinline__ uint32_t smem_u32(const void* p) {
    uint32_t a;
    asm("{ .reg .u64 t; cvta.to.shared.u64 t, %1; cvt.u32.u64 %0, t; }" : "=r"(a) : "l"(p));
    return a;
}

#define CP_ASYNC16(dst, src) \
    asm volatile("cp.async.cg.shared.global [%0], [%1], 16;" :: "r"(dst), "l"(src) : "memory")
#define CP_COMMIT() asm volatile("cp.async.commit_group;" ::: "memory")
#define CP_WAIT_0() asm volatile("cp.async.wait_group 0;" ::: "memory")

#define LDMATRIX_X4(r0, r1, r2, r3, addr) \
    asm volatile("ldmatrix.sync.aligned.m8n8.x4.shared.b16 {%0,%1,%2,%3}, [%4];" \
                 : "=r"(r0), "=r"(r1), "=r"(r2), "=r"(r3) : "r"(addr))

#define MMA_BF16(d, a0, a1, a2, a3, b0, b1) \
    asm volatile("mma.sync.aligned.m16n8k16.row.col.f32.bf16.bf16.f32 " \
                 "{%0,%1,%2,%3}, {%4,%5,%6,%7}, {%8,%9}, {%0,%1,%2,%3};" \
                 : "+f"((d)[0]), "+f"((d)[1]), "+f"((d)[2]), "+f"((d)[3]) \
                 : "r"(a0), "r"(a1), "r"(a2), "r"(a3), "r"(b0), "r"(b1))

__device__ __forceinline__ uint32_t pack_bf16(float a, float b) {
    __nv_bfloat162 t;
    t.x = __float2bfloat16_rn(a);
    t.y = __float2bfloat16_rn(b);
    return *reinterpret_cast<uint32_t*>(&t);
}

// ---------------- Stage 0: build transposed split W ----------------
__global__ __launch_bounds__(256)
void split_w_kernel(const float* __restrict__ W1,
                    __nv_bfloat16* __restrict__ WhT,
                    __nv_bfloat16* __restrict__ WlT) {
    int idx = blockIdx.x * blockDim.x + threadIdx.x;
    if (idx >= 256 * 256) return;
    int n = idx & 255;
    int k = idx >> 8;
    float val = (n < HH) ? W1[(size_t)k * HH + n]
                         : W1[(size_t)(256 + k) * HH + (n - HH)];
    __nv_bfloat16 h = __float2bfloat16_rn(val);
    __nv_bfloat16 l = __float2bfloat16_rn(val - __bfloat162float(h));
    WhT[(size_t)n * 256 + k] = h;
    WlT[(size_t)n * 256 + k] = l;
}

// ---------------- Stage 1: fused split + bf16 HMMA GEMM ----------------
// SMEM (192 KB):
//   A32      [128 x 64 fp32]  @ 0       (32 KB, single buffer)
//   Ah       [128 x 64 bf16]  @ 32768   (16 KB)
//   Al       [128 x 64 bf16]  @ 49152   (16 KB)
//   Bh stage [256 x 64 bf16]  @ 65536 + s*65536       (32 KB each)
//   Bl stage [256 x 64 bf16]  @ 65536 + s*65536 + 32768
#define A32_OFF 0
#define AH_OFF  32768
#define AL_OFF  49152
#define BH_OFF(s) (65536 + (s) * 65536)
#define BL_OFF(s) (65536 + (s) * 65536 + 32768)
#define GSM_TOTAL 196608

__global__ __launch_bounds__(256, 1)
void uv_gemm_fused_kernel(const float* __restrict__ Z,
                          const __nv_bfloat16* __restrict__ WhT,
                          const __nv_bfloat16* __restrict__ WlT,
                          const float* __restrict__ b1,
                          __half* __restrict__ UV,
                          int M) {
    extern __shared__ char smem[];
    const uint32_t sbase = smem_u32(smem);
    const int tid  = threadIdx.x;
    const int wid  = tid >> 5;
    const int lane = tid & 31;
    const int wm   = wid & 3;          // 4 warp-row groups: 32 rows each
    const int wn   = wid >> 2;         // 2 warp-col groups: 128 cols each
    const int row0 = blockIdx.x * 128;

    const int g  = lane >> 3;          // 0..3
    const int lr = lane & 7;
    const int uAbit = g >> 1;
    const int uBbit = g & 1;
    const int rA0 = wm * 32 + (g & 1) * 8 + lr;
    const int nB0 = wn * 128 + (g >> 1) * 8 + lr;

    float acc[2][16][4];
#pragma unroll
    for (int mi = 0; mi < 2; mi++)
#pragma unroll
        for (int ni = 0; ni < 16; ni++)
#pragma unroll
            for (int q = 0; q < 4; q++) acc[mi][ni][q] = 0.f;

    // issue loads for chunk c: A32 (fp32 Z) + Bh/Bl into stage c&1
    auto issue_loads = [&](int c) {
        const int kc = c * 64;
        const int s  = c & 1;
        // A32: 128 rows x 256B, plain layout; 2048 x 16B over 256 thr
#pragma unroll
        for (int i = 0; i < 8; ++i) {
            int idx = tid + i * 256;
            int r = idx >> 4;
            int q = idx & 15;
            int gr = row0 + r; if (gr > M - 1) gr = M - 1;
            CP_ASYNC16(sbase + A32_OFF + (uint32_t)(r * 256 + q * 16),
                       Z + (size_t)gr * 256 + kc + q * 4);
        }
        // Bh / Bl: 256 rows x 128B swizzled; 2048 x 16B each
#pragma unroll
        for (int i = 0; i < 8; ++i) {
            int idx = tid + i * 256;
            int n = idx >> 3;
            int u = idx & 7;
            uint32_t soff = (uint32_t)(n * 128 + ((u ^ (n & 7)) << 4));
            CP_ASYNC16(sbase + BH_OFF(s) + soff, WhT + (size_t)n * 256 + kc + u * 8);
            CP_ASYNC16(sbase + BL_OFF(s) + soff, WlT + (size_t)n * 256 + kc + u * 8);
        }
        CP_COMMIT();
    };

    issue_loads(0);

    for (int c = 0; c < 4; ++c) {
        CP_WAIT_0();
        __syncthreads();

        // convert A32 -> Ah/Al (swizzled bf16, 128B rows)
#pragma unroll
        for (int i = 0; i < 8; ++i) {
            int idx = tid + i * 256;
            int r = idx >> 4;
            int q = idx & 15;                       // float4 index in row
            float4 f = *reinterpret_cast<const float4*>(smem + A32_OFF + r * 256 + q * 16);
            uint2 hv, lv;
            {
                float hx = __bfloat162float(__float2bfloat16_rn(f.x));
                float hy = __bfloat162float(__float2bfloat16_rn(f.y));
                float hz = __bfloat162float(__float2bfloat16_rn(f.z));
                float hw = __bfloat162float(__float2bfloat16_rn(f.w));
                hv.x = pack_bf16(f.x, f.y);
                hv.y = pack_bf16(f.z, f.w);
                lv.x = pack_bf16(f.x - hx, f.y - hy);
                lv.y = pack_bf16(f.z - hz, f.w - hw);
            }
            uint32_t soff = (uint32_t)(r * 128 + (((q >> 1) ^ (r & 7)) << 4) + (q & 1) * 8);
            *reinterpret_cast<uint2*>(smem + AH_OFF + soff) = hv;
            *reinterpret_cast<uint2*>(smem + AL_OFF + soff) = lv;
        }
        __syncthreads();

        if (c < 3) issue_loads(c + 1);   // overlaps with MMA below

        const uint32_t bhBase = sbase + BH_OFF(c & 1);
        const uint32_t blBase = sbase + BL_OFF(c & 1);

#pragma unroll
        for (int kk = 0; kk < 4; ++kk) {
            uint32_t afh[2][4], afl[2][4];
#pragma unroll
            for (int mi = 0; mi < 2; ++mi) {
                int r = rA0 + mi * 16;
                uint32_t aoff = (uint32_t)(r * 128 + (((kk * 2 + uAbit) ^ lr) << 4));
                LDMATRIX_X4(afh[mi][0], afh[mi][1], afh[mi][2], afh[mi][3],
                            sbase + AH_OFF + aoff);
                LDMATRIX_X4(afl[mi][0], afl[mi][1], afl[mi][2], afl[mi][3],
                            sbase + AL_OFF + aoff);
            }
#pragma unroll
            for (int np = 0; np < 8; ++np) {
                int n = nB0 + np * 16;
                uint32_t boff = (uint32_t)(n * 128 + (((kk * 2 + uBbit) ^ lr) << 4));
                uint32_t bh0, bh1, bh2, bh3, bl0, bl1, bl2, bl3;
                LDMATRIX_X4(bh0, bh1, bh2, bh3, bhBase + boff);
                LDMATRIX_X4(bl0, bl1, bl2, bl3, blBase + boff);
#pragma unroll
                for (int mi = 0; mi < 2; ++mi) {
                    MMA_BF16(acc[mi][np * 2],     afh[mi][0], afh[mi][1], afh[mi][2], afh[mi][3], bh0, bh1);
                    MMA_BF16(acc[mi][np * 2 + 1], afh[mi][0], afh[mi][1], afh[mi][2], afh[mi][3], bh2, bh3);
                    MMA_BF16(acc[mi][np * 2],     afh[mi][0], afh[mi][1], afh[mi][2], afh[mi][3], bl0, bl1);
                    MMA_BF16(acc[mi][np * 2 + 1], afh[mi][0], afh[mi][1], afh[mi][2], afh[mi][3], bl2, bl3);
                    MMA_BF16(acc[mi][np * 2],     afl[mi][0], afl[mi][1], afl[mi][2], afl[mi][3], bh0, bh1);
                    MMA_BF16(acc[mi][np * 2 + 1], afl[mi][0], afl[mi][1], afl[mi][2], afl[mi][3], bh2, bh3);
                }
            }
        }
        __syncthreads();   // Ah/Al + A32 reused next chunk
    }

    // ---- epilogue: +b1 on cols<128, store fp16 ----
    const int trow  = lane >> 2;
    const int tcol2 = (lane & 3) * 2;
#pragma unroll
    for (int mi = 0; mi < 2; ++mi) {
#pragma unroll
        for (int ni = 0; ni < 16; ++ni) {
            int col = wn * 128 + ni * 8 + tcol2;
            float bx = 0.f, by = 0.f;
            if (col < HH) { bx = __ldg(&b1[col]); by = __ldg(&b1[col + 1]); }
#pragma unroll
            for (int h = 0; h < 2; ++h) {
                int r = row0 + wm * 32 + mi * 16 + trow + h * 8;
                if (r < M) {
                    __half2 v = __floats2half2_rn(acc[mi][ni][h * 2] + bx,
                                                  acc[mi][ni][h * 2 + 1] + by);
                    *reinterpret_cast<__half2*>(UV + (size_t)r * 256 + col) = v;
                }
            }
        }
    }
}

// ---------------- Stage 2: 4 edges per warp, fp16 UV ----------------
__global__ __launch_bounds__(256)
void edge_kernel(const int* __restrict__ eli,
                 const __half* __restrict__ UV,
                 const float* __restrict__ W2,
                 const float* __restrict__ b2,
                 float* __restrict__ out,
                 int E) {
    int gwarp = (blockIdx.x * blockDim.x + threadIdx.x) >> 5;
    int lane  = threadIdx.x & 31;
    int e0 = gwarp * 4;
    if (e0 >= E) return;

    float4 w = __ldg(reinterpret_cast<const float4*>(W2) + lane);

    int s[4], d[4];
#pragma unroll
    for (int i = 0; i < 4; ++i) {
        int e = min(e0 + i, E - 1);
        s[i] = __ldg(&eli[e]);
        d[i] = __ldg(&eli[(size_t)E + e]);
    }
    uint2 ur[4], vr[4];
#pragma unroll
    for (int i = 0; i < 4; ++i) {
        ur[i] = __ldg(reinterpret_cast<const uint2*>(UV + (size_t)s[i] * 256) + lane);
        vr[i] = __ldg(reinterpret_cast<const uint2*>(UV + (size_t)d[i] * 256 + HH) + lane);
    }
    float p[4];
#pragma unroll
    for (int i = 0; i < 4; ++i) {
        const __half2* uh = reinterpret_cast<const __half2*>(&ur[i]);
        const __half2* vh = reinterpret_cast<const __half2*>(&vr[i]);
        float2 u01 = __half22float2(uh[0]);
        float2 u23 = __half22float2(uh[1]);
        float2 v01 = __half22float2(vh[0]);
        float2 v23 = __half22float2(vh[1]);
        p[i] = fmaxf(u01.x + v01.x, 0.f) * w.x + fmaxf(u01.y + v01.y, 0.f) * w.y
             + fmaxf(u23.x + v23.x, 0.f) * w.z + fmaxf(u23.y + v23.y, 0.f) * w.w;
    }
#pragma unroll
    for (int o = 16; o > 0; o >>= 1) {
#pragma unroll
        for (int i = 0; i < 4; ++i)
            p[i] += __shfl_down_sync(0xffffffffu, p[i], o);
    }
    if (lane == 0) {
        float bb = __ldg(b2);
#pragma unroll
        for (int i = 0; i < 4; ++i)
            if (e0 + i < E) out[e0 + i] = p[i] + bb;
    }
}

extern "C" void kernel_launch(void* const* d_in, const int* in_sizes, int n_in,
                              void* d_out, int out_size) {
    const float* z   = (const float*)d_in[0];
    const int*   eli = (const int*)d_in[1];
    const float* W1  = (const float*)d_in[2];
    const float* b1  = (const float*)d_in[3];
    const float* W2  = (const float*)d_in[4];
    const float* b2  = (const float*)d_in[5];
    float*       out = (float*)d_out;

    const int M = in_sizes[0] / DD;
    const int E = out_size;

    __half* UV; __nv_bfloat16 *WhT, *WlT;
    cudaGetSymbolAddress((void**)&UV,  g_UV);
    cudaGetSymbolAddress((void**)&WhT, g_WhT);
    cudaGetSymbolAddress((void**)&WlT, g_WlT);

    cudaFuncSetAttribute(uv_gemm_fused_kernel,
                         cudaFuncAttributeMaxDynamicSharedMemorySize, GSM_TOTAL);

    split_w_kernel<<<(256 * 256 + 255) / 256, 256>>>(W1, WhT, WlT);

    int gblocks = (M + 127) / 128;
    uv_gemm_fused_kernel<<<gblocks, 256, GSM_TOTAL>>>(z, WhT, WlT, b1, UV, M);

    int quads = (E + 3) / 4;
    int warpsPerBlock = 256 / 32;
    int nblk = (quads + warpsPerBlock - 1) / warpsPerBlock;
    edge_kernel<<<nblk, 256>>>(eli, UV, W2, b2, out, E);
}

// round 7
// speedup vs baseline: 2.6379x; 1.1064x over previous
#include <cuda_runtime.h>
#include <cuda_bf16.h>
#include <cuda_fp16.h>
#include <cstdint>

// LinkPredictorGAT: N_NODES=100000, D=256, E=1000000, H=128
// out_e = relu(z[src]@W1[:256] + z[dst]@W1[256:] + b1) @ W2 + b2
//
// Stage 0: W1 -> WhT,WlT bf16 hi/lo, transposed to [N=256,K=256] K-major.
// Stage 1: fused GEMM (mma.sync bf16, 3-term split): LDG Z fp32 -> regs -> cvt ->
//          STS Ah/Al (double-buffered), cp.async Bh/Bl (double-buffered).
//          UV[M,256](fp16) = Zh@Wh + Zh@Wl + Zl@Wh (+b1 on cols<128).
// Stage 2: 4 edges/warp on fp16 UV: out = relu(u[src]+v[dst]) . W2 + b2

#define MAX_NODES 100000
#define DD 256
#define HH 128

__device__ __half        g_UV [(size_t)MAX_NODES * 2 * HH];     // 51.2 MB
__device__ __nv_bfloat16 g_WhT[256 * 256];
__device__ __nv_bfloat16 g_WlT[256 * 256];

__device__ __forceinline__ uint32_t smem_u32(const void* p) {
    uint32_t a;
    asm("{ .reg .u64 t; cvta.to.shared.u64 t, %1; cvt.u32.u64 %0, t; }" : "=r"(a) : "l"(p));
    return a;
}

#define CP_ASYNC16(dst, src) \
    asm volatile("cp.async.cg.shared.global [%0], [%1], 16;" :: "r"(dst), "l"(src) : "memory")
#define CP_COMMIT() asm volatile("cp.async.commit_group;" ::: "memory")
#define CP_WAIT_0() asm volatile("cp.async.wait_group 0;" ::: "memory")

#define LDMATRIX_X4(r0, r1, r2, r3, addr) \
    asm volatile("ldmatrix.sync.aligned.m8n8.x4.shared.b16 {%0,%1,%2,%3}, [%4];" \
                 : "=r"(r0), "=r"(r1), "=r"(r2), "=r"(r3) : "r"(addr))

#define MMA_BF16(d, a0, a1, a2, a3, b0, b1) \
    asm volatile("mma.sync.aligned.m16n8k16.row.col.f32.bf16.bf16.f32 " \
                 "{%0,%1,%2,%3}, {%4,%5,%6,%7}, {%8,%9}, {%0,%1,%2,%3};" \
                 : "+f"((d)[0]), "+f"((d)[1]), "+f"((d)[2]), "+f"((d)[3]) \
                 : "r"(a0), "r"(a1), "r"(a2), "r"(a3), "r"(b0), "r"(b1))

__device__ __forceinline__ uint32_t pack_bf16(float a, float b) {
    __nv_bfloat162 t;
    t.x = __float2bfloat16_rn(a);
    t.y = __float2bfloat16_rn(b);
    return *reinterpret_cast<uint32_t*>(&t);
}

// ---------------- Stage 0: build transposed split W ----------------
__global__ __launch_bounds__(256)
void split_w_kernel(const float* __restrict__ W1,
                    __nv_bfloat16* __restrict__ WhT,
                    __nv_bfloat16* __restrict__ WlT) {
    int idx = blockIdx.x * blockDim.x + threadIdx.x;
    if (idx >= 256 * 256) return;
    int n = idx & 255;
    int k = idx >> 8;
    float val = (n < HH) ? W1[(size_t)k * HH + n]
                         : W1[(size_t)(256 + k) * HH + (n - HH)];
    __nv_bfloat16 h = __float2bfloat16_rn(val);
    __nv_bfloat16 l = __float2bfloat16_rn(val - __bfloat162float(h));
    WhT[(size_t)n * 256 + k] = h;
    WlT[(size_t)n * 256 + k] = l;
}

// ---------------- Stage 1: fused split + bf16 HMMA GEMM ----------------
// SMEM (192 KB), stages s in {0,1}:
//   Ah(s) @ s*32768,            Al(s) @ s*32768 + 16384        [0, 64K)
//   Bh(s) @ 65536 + s*65536,    Bl(s) @ 65536 + s*65536 + 32768
#define AH_OFF(s) ((s) * 32768)
#define AL_OFF(s) ((s) * 32768 + 16384)
#define BH_OFF(s) (65536 + (s) * 65536)
#define BL_OFF(s) (65536 + (s) * 65536 + 32768)
#define GSM_TOTAL 196608

__global__ __launch_bounds__(256, 1)
void uv_gemm_fused_kernel(const float* __restrict__ Z,
                          const __nv_bfloat16* __restrict__ WhT,
                          const __nv_bfloat16* __restrict__ WlT,
                          const float* __restrict__ b1,
                          __half* __restrict__ UV,
                          int M) {
    extern __shared__ char smem[];
    const uint32_t sbase = smem_u32(smem);
    const int tid  = threadIdx.x;
    const int wid  = tid >> 5;
    const int lane = tid & 31;
    const int wm   = wid & 3;          // 4 warp-row groups: 32 rows each
    const int wn   = wid >> 2;         // 2 warp-col groups: 128 cols each
    const int row0 = blockIdx.x * 128;

    const int g  = lane >> 3;
    const int lr = lane & 7;
    const int uAbit = g >> 1;
    const int uBbit = g & 1;
    const int rA0 = wm * 32 + (g & 1) * 8 + lr;
    const int nB0 = wn * 128 + (g >> 1) * 8 + lr;

    // LDG/STS lane decomposition for A: idx = tid + i*256, i<8
    //   r = idx>>4 (0..127), q = idx&15 (float4 within 64-float row chunk)
    const int ar = -1; // (computed per i below)
    (void)ar;

    float acc[2][16][4];
#pragma unroll
    for (int mi = 0; mi < 2; mi++)
#pragma unroll
        for (int ni = 0; ni < 16; ni++)
#pragma unroll
            for (int q = 0; q < 4; q++) acc[mi][ni][q] = 0.f;

    // ---- helpers ----
    auto ldg_A = [&](int c, float4 (&rA)[8]) {
        const int kc = c * 64;
#pragma unroll
        for (int i = 0; i < 8; ++i) {
            int idx = tid + i * 256;
            int r = idx >> 4;
            int q = idx & 15;
            int gr = row0 + r; if (gr > M - 1) gr = M - 1;
            rA[i] = __ldg(reinterpret_cast<const float4*>(Z + (size_t)gr * 256 + kc + q * 4));
        }
    };
    auto sts_A = [&](int s, const float4 (&rA)[8]) {
#pragma unroll
        for (int i = 0; i < 8; ++i) {
            int idx = tid + i * 256;
            int r = idx >> 4;
            int q = idx & 15;
            float4 f = rA[i];
            float hx = __bfloat162float(__float2bfloat16_rn(f.x));
            float hy = __bfloat162float(__float2bfloat16_rn(f.y));
            float hz = __bfloat162float(__float2bfloat16_rn(f.z));
            float hw = __bfloat162float(__float2bfloat16_rn(f.w));
            uint2 hv, lv;
            hv.x = pack_bf16(f.x, f.y);
            hv.y = pack_bf16(f.z, f.w);
            lv.x = pack_bf16(f.x - hx, f.y - hy);
            lv.y = pack_bf16(f.z - hz, f.w - hw);
            uint32_t soff = (uint32_t)(r * 128 + (((q >> 1) ^ (r & 7)) << 4) + (q & 1) * 8);
            *reinterpret_cast<uint2*>(smem + AH_OFF(s) + soff) = hv;
            *reinterpret_cast<uint2*>(smem + AL_OFF(s) + soff) = lv;
        }
    };
    auto issue_B = [&](int c) {
        const int kc = c * 64;
        const int s  = c & 1;
#pragma unroll
        for (int i = 0; i < 8; ++i) {
            int idx = tid + i * 256;
            int n = idx >> 3;
            int u = idx & 7;
            uint32_t soff = (uint32_t)(n * 128 + ((u ^ (n & 7)) << 4));
            CP_ASYNC16(sbase + BH_OFF(s) + soff, WhT + (size_t)n * 256 + kc + u * 8);
            CP_ASYNC16(sbase + BL_OFF(s) + soff, WlT + (size_t)n * 256 + kc + u * 8);
        }
        CP_COMMIT();
    };

    // ---- prologue ----
    float4 rA[8];
    ldg_A(0, rA);
    issue_B(0);
    sts_A(0, rA);
    ldg_A(1, rA);

    for (int c = 0; c < 4; ++c) {
        CP_WAIT_0();            // B(c) landed (this thread's copies)
        __syncthreads();        // everyone's B(c)+A(c) visible; stage (c+1)&1 readers done

        if (c < 3) issue_B(c + 1);   // lands during MMA(c)

        const int s = c & 1;
        const uint32_t ahBase = sbase + AH_OFF(s);
        const uint32_t alBase = sbase + AL_OFF(s);
        const uint32_t bhBase = sbase + BH_OFF(s);
        const uint32_t blBase = sbase + BL_OFF(s);

#pragma unroll
        for (int kk = 0; kk < 4; ++kk) {
            uint32_t afh[2][4], afl[2][4];
#pragma unroll
            for (int mi = 0; mi < 2; ++mi) {
                int r = rA0 + mi * 16;
                uint32_t aoff = (uint32_t)(r * 128 + (((kk * 2 + uAbit) ^ lr) << 4));
                LDMATRIX_X4(afh[mi][0], afh[mi][1], afh[mi][2], afh[mi][3], ahBase + aoff);
                LDMATRIX_X4(afl[mi][0], afl[mi][1], afl[mi][2], afl[mi][3], alBase + aoff);
            }
#pragma unroll
            for (int np = 0; np < 8; ++np) {
                int n = nB0 + np * 16;
                uint32_t boff = (uint32_t)(n * 128 + (((kk * 2 + uBbit) ^ lr) << 4));
                uint32_t bh0, bh1, bh2, bh3, bl0, bl1, bl2, bl3;
                LDMATRIX_X4(bh0, bh1, bh2, bh3, bhBase + boff);
                LDMATRIX_X4(bl0, bl1, bl2, bl3, blBase + boff);
#pragma unroll
                for (int mi = 0; mi < 2; ++mi) {
                    MMA_BF16(acc[mi][np * 2],     afh[mi][0], afh[mi][1], afh[mi][2], afh[mi][3], bh0, bh1);
                    MMA_BF16(acc[mi][np * 2 + 1], afh[mi][0], afh[mi][1], afh[mi][2], afh[mi][3], bh2, bh3);
                    MMA_BF16(acc[mi][np * 2],     afh[mi][0], afh[mi][1], afh[mi][2], afh[mi][3], bl0, bl1);
                    MMA_BF16(acc[mi][np * 2 + 1], afh[mi][0], afh[mi][1], afh[mi][2], afh[mi][3], bl2, bl3);
                    MMA_BF16(acc[mi][np * 2],     afl[mi][0], afl[mi][1], afl[mi][2], afl[mi][3], bh0, bh1);
                    MMA_BF16(acc[mi][np * 2 + 1], afl[mi][0], afl[mi][1], afl[mi][2], afl[mi][3], bh2, bh3);
                }
            }
        }

        // tail: stage A(c+1) into the other buffer; prefetch A(c+2)
        if (c < 3) {
            sts_A((c + 1) & 1, rA);
            if (c < 2) ldg_A(c + 2, rA);
        }
    }

    // ---- epilogue: +b1 on cols<128, store fp16 ----
    const int trow  = lane >> 2;
    const int tcol2 = (lane & 3) * 2;
#pragma unroll
    for (int mi = 0; mi < 2; ++mi) {
#pragma unroll
        for (int ni = 0; ni < 16; ++ni) {
            int col = wn * 128 + ni * 8 + tcol2;
            float bx = 0.f, by = 0.f;
            if (col < HH) { bx = __ldg(&b1[col]); by = __ldg(&b1[col + 1]); }
#pragma unroll
            for (int h = 0; h < 2; ++h) {
                int r = row0 + wm * 32 + mi * 16 + trow + h * 8;
                if (r < M) {
                    __half2 v = __floats2half2_rn(acc[mi][ni][h * 2] + bx,
                                                  acc[mi][ni][h * 2 + 1] + by);
                    *reinterpret_cast<__half2*>(UV + (size_t)r * 256 + col) = v;
                }
            }
        }
    }
}

// ---------------- Stage 2: 4 edges per warp, fp16 UV ----------------
__global__ __launch_bounds__(256)
void edge_kernel(const int* __restrict__ eli,
                 const __half* __restrict__ UV,
                 const float* __restrict__ W2,
                 const float* __restrict__ b2,
                 float* __restrict__ out,
                 int E) {
    int gwarp = (blockIdx.x * blockDim.x + threadIdx.x) >> 5;
    int lane  = threadIdx.x & 31;
    int e0 = gwarp * 4;
    if (e0 >= E) return;

    float4 w = __ldg(reinterpret_cast<const float4*>(W2) + lane);

    int s[4], d[4];
#pragma unroll
    for (int i = 0; i < 4; ++i) {
        int e = min(e0 + i, E - 1);
        s[i] = __ldg(&eli[e]);
        d[i] = __ldg(&eli[(size_t)E + e]);
    }
    uint2 ur[4], vr[4];
#pragma unroll
    for (int i = 0; i < 4; ++i) {
        ur[i] = __ldg(reinterpret_cast<const uint2*>(UV + (size_t)s[i] * 256) + lane);
        vr[i] = __ldg(reinterpret_cast<const uint2*>(UV + (size_t)d[i] * 256 + HH) + lane);
    }
    float p[4];
#pragma unroll
    for (int i = 0; i < 4; ++i) {
        const __half2* uh = reinterpret_cast<const __half2*>(&ur[i]);
        const __half2* vh = reinterpret_cast<const __half2*>(&vr[i]);
        float2 u01 = __half22float2(uh[0]);
        float2 u23 = __half22float2(uh[1]);
        float2 v01 = __half22float2(vh[0]);
        float2 v23 = __half22float2(vh[1]);
        p[i] = fmaxf(u01.x + v01.x, 0.f) * w.x + fmaxf(u01.y + v01.y, 0.f) * w.y
             + fmaxf(u23.x + v23.x, 0.f) * w.z + fmaxf(u23.y + v23.y, 0.f) * w.w;
    }
#pragma unroll
    for (int o = 16; o > 0; o >>= 1) {
#pragma unroll
        for (int i = 0; i < 4; ++i)
            p[i] += __shfl_down_sync(0xffffffffu, p[i], o);
    }
    if (lane == 0) {
        float bb = __ldg(b2);
#pragma unroll
        for (int i = 0; i < 4; ++i)
            if (e0 + i < E) out[e0 + i] = p[i] + bb;
    }
}

extern "C" void kernel_launch(void* const* d_in, const int* in_sizes, int n_in,
                              void* d_out, int out_size) {
    const float* z   = (const float*)d_in[0];
    const int*   eli = (const int*)d_in[1];
    const float* W1  = (const float*)d_in[2];
    const float* b1  = (const float*)d_in[3];
    const float* W2  = (const float*)d_in[4];
    const float* b2  = (const float*)d_in[5];
    float*       out = (float*)d_out;

    const int M = in_sizes[0] / DD;
    const int E = out_size;

    __half* UV; __nv_bfloat16 *WhT, *WlT;
    cudaGetSymbolAddress((void**)&UV,  g_UV);
    cudaGetSymbolAddress((void**)&WhT, g_WhT);
    cudaGetSymbolAddress((void**)&WlT, g_WlT);

    cudaFuncSetAttribute(uv_gemm_fused_kernel,
                         cudaFuncAttributeMaxDynamicSharedMemorySize, GSM_TOTAL);

    split_w_kernel<<<(256 * 256 + 255) / 256, 256>>>(W1, WhT, WlT);

    int gblocks = (M + 127) / 128;
    uv_gemm_fused_kernel<<<gblocks, 256, GSM_TOTAL>>>(z, WhT, WlT, b1, UV, M);

    int quads = (E + 3) / 4;
    int warpsPerBlock = 256 / 32;
    int nblk = (quads + warpsPerBlock - 1) / warpsPerBlock;
    edge_kernel<<<nblk, 256>>>(eli, UV, W2, b2, out, E);
}

// round 8
// speedup vs baseline: 3.2004x; 1.2132x over previous
#include <cuda_runtime.h>
#include <cuda_bf16.h>
#include <cuda_fp16.h>
#include <cstdint>

// LinkPredictorGAT: N_NODES=100000, D=256, E=1000000, H=128
// out_e = relu(z[src]@W1[:256] + z[dst]@W1[256:] + b1) @ W2 + b2
//
// Stage 0: W1 -> WT fp16, transposed to [N=256,K=256] K-major.
// Stage 1: fused GEMM (mma.sync fp16, 2-term split): LDG Z fp32 -> regs ->
//          split zh/zl fp16 -> STS (double-buffered); cp.async W (double-buffered).
//          UV[M,256](fp16) = Zh@W16 + Zl@W16 (+b1 on cols<128).
// Stage 2: 4 edges/warp on fp16 UV: out = relu(u[src]+v[dst]) . W2 + b2

#define MAX_NODES 100000
#define DD 256
#define HH 128

__device__ __half g_UV[(size_t)MAX_NODES * 2 * HH];     // 51.2 MB
__device__ __half g_WT[256 * 256];                      // 128 KB

__device__ __forceinline__ uint32_t smem_u32(const void* p) {
    uint32_t a;
    asm("{ .reg .u64 t; cvta.to.shared.u64 t, %1; cvt.u32.u64 %0, t; }" : "=r"(a) : "l"(p));
    return a;
}

#define CP_ASYNC16(dst, src) \
    asm volatile("cp.async.cg.shared.global [%0], [%1], 16;" :: "r"(dst), "l"(src) : "memory")
#define CP_COMMIT() asm volatile("cp.async.commit_group;" ::: "memory")
#define CP_WAIT_0() asm volatile("cp.async.wait_group 0;" ::: "memory")

#define LDMATRIX_X4(r0, r1, r2, r3, addr) \
    asm volatile("ldmatrix.sync.aligned.m8n8.x4.shared.b16 {%0,%1,%2,%3}, [%4];" \
                 : "=r"(r0), "=r"(r1), "=r"(r2), "=r"(r3) : "r"(addr))

#define MMA_F16(d, a0, a1, a2, a3, b0, b1) \
    asm volatile("mma.sync.aligned.m16n8k16.row.col.f32.f16.f16.f32 " \
                 "{%0,%1,%2,%3}, {%4,%5,%6,%7}, {%8,%9}, {%0,%1,%2,%3};" \
                 : "+f"((d)[0]), "+f"((d)[1]), "+f"((d)[2]), "+f"((d)[3]) \
                 : "r"(a0), "r"(a1), "r"(a2), "r"(a3), "r"(b0), "r"(b1))

// ---------------- Stage 0: build transposed fp16 W ----------------
__global__ __launch_bounds__(256)
void split_w_kernel(const float* __restrict__ W1, __half* __restrict__ WT) {
    int idx = blockIdx.x * blockDim.x + threadIdx.x;
    if (idx >= 256 * 256) return;
    int n = idx & 255;
    int k = idx >> 8;
    float val = (n < HH) ? W1[(size_t)k * HH + n]
                         : W1[(size_t)(256 + k) * HH + (n - HH)];
    WT[(size_t)n * 256 + k] = __float2half_rn(val);
}

// ---------------- Stage 1: fused split + fp16 HMMA GEMM ----------------
// SMEM (128 KB), stages s in {0,1}:
//   Ah(s) @ s*32768, Al(s) @ s*32768+16384   [0, 64K)
//   B(s)  @ 65536 + s*32768                  [64K, 128K)
#define AH_OFF(s) ((s) * 32768)
#define AL_OFF(s) ((s) * 32768 + 16384)
#define B_OFF(s)  (65536 + (s) * 32768)
#define GSM_TOTAL 131072

__global__ __launch_bounds__(256, 1)
void uv_gemm_fused_kernel(const float* __restrict__ Z,
                          const __half* __restrict__ WT,
                          const float* __restrict__ b1,
                          __half* __restrict__ UV,
                          int M) {
    extern __shared__ char smem[];
    const uint32_t sbase = smem_u32(smem);
    const int tid  = threadIdx.x;
    const int wid  = tid >> 5;
    const int lane = tid & 31;
    const int wm   = wid & 3;          // 4 warp-row groups: 32 rows each
    const int wn   = wid >> 2;         // 2 warp-col groups: 128 cols each
    const int row0 = blockIdx.x * 128;

    const int g  = lane >> 3;
    const int lr = lane & 7;
    const int uAbit = g >> 1;
    const int uBbit = g & 1;
    const int rA0 = wm * 32 + (g & 1) * 8 + lr;
    const int nB0 = wn * 128 + (g >> 1) * 8 + lr;

    float acc[2][16][4];
#pragma unroll
    for (int mi = 0; mi < 2; mi++)
#pragma unroll
        for (int ni = 0; ni < 16; ni++)
#pragma unroll
            for (int q = 0; q < 4; q++) acc[mi][ni][q] = 0.f;

    auto ldg_A = [&](int c, float4 (&rA)[8]) {
        const int kc = c * 64;
#pragma unroll
        for (int i = 0; i < 8; ++i) {
            int idx = tid + i * 256;
            int r = idx >> 4;
            int q = idx & 15;
            int gr = row0 + r; if (gr > M - 1) gr = M - 1;
            rA[i] = __ldg(reinterpret_cast<const float4*>(Z + (size_t)gr * 256 + kc + q * 4));
        }
    };
    auto sts_A = [&](int s, const float4 (&rA)[8]) {
#pragma unroll
        for (int i = 0; i < 8; ++i) {
            int idx = tid + i * 256;
            int r = idx >> 4;
            int q = idx & 15;
            float4 f = rA[i];
            __half hx = __float2half_rn(f.x);
            __half hy = __float2half_rn(f.y);
            __half hz = __float2half_rn(f.z);
            __half hw = __float2half_rn(f.w);
            __half2 h01 = __halves2half2(hx, hy);
            __half2 h23 = __halves2half2(hz, hw);
            __half2 l01 = __floats2half2_rn(f.x - __half2float(hx), f.y - __half2float(hy));
            __half2 l23 = __floats2half2_rn(f.z - __half2float(hz), f.w - __half2float(hw));
            uint2 hv = make_uint2(*reinterpret_cast<uint32_t*>(&h01),
                                  *reinterpret_cast<uint32_t*>(&h23));
            uint2 lv = make_uint2(*reinterpret_cast<uint32_t*>(&l01),
                                  *reinterpret_cast<uint32_t*>(&l23));
            uint32_t soff = (uint32_t)(r * 128 + (((q >> 1) ^ (r & 7)) << 4) + (q & 1) * 8);
            *reinterpret_cast<uint2*>(smem + AH_OFF(s) + soff) = hv;
            *reinterpret_cast<uint2*>(smem + AL_OFF(s) + soff) = lv;
        }
    };
    auto issue_B = [&](int c) {
        const int kc = c * 64;
        const int s  = c & 1;
#pragma unroll
        for (int i = 0; i < 8; ++i) {
            int idx = tid + i * 256;
            int n = idx >> 3;
            int u = idx & 7;
            uint32_t soff = (uint32_t)(n * 128 + ((u ^ (n & 7)) << 4));
            CP_ASYNC16(sbase + B_OFF(s) + soff, WT + (size_t)n * 256 + kc + u * 8);
        }
        CP_COMMIT();
    };

    // ---- prologue ----
    float4 rA[8];
    ldg_A(0, rA);
    issue_B(0);
    sts_A(0, rA);
    ldg_A(1, rA);

    for (int c = 0; c < 4; ++c) {
        CP_WAIT_0();
        __syncthreads();

        if (c < 3) issue_B(c + 1);

        const int s = c & 1;
        const uint32_t ahBase = sbase + AH_OFF(s);
        const uint32_t alBase = sbase + AL_OFF(s);
        const uint32_t bBase  = sbase + B_OFF(s);

#pragma unroll
        for (int kk = 0; kk < 4; ++kk) {
            uint32_t afh[2][4], afl[2][4];
#pragma unroll
            for (int mi = 0; mi < 2; ++mi) {
                int r = rA0 + mi * 16;
                uint32_t aoff = (uint32_t)(r * 128 + (((kk * 2 + uAbit) ^ lr) << 4));
                LDMATRIX_X4(afh[mi][0], afh[mi][1], afh[mi][2], afh[mi][3], ahBase + aoff);
                LDMATRIX_X4(afl[mi][0], afl[mi][1], afl[mi][2], afl[mi][3], alBase + aoff);
            }
#pragma unroll
            for (int np = 0; np < 8; ++np) {
                int n = nB0 + np * 16;
                uint32_t boff = (uint32_t)(n * 128 + (((kk * 2 + uBbit) ^ lr) << 4));
                uint32_t b0, b1r, b2, b3;
                LDMATRIX_X4(b0, b1r, b2, b3, bBase + boff);
#pragma unroll
                for (int mi = 0; mi < 2; ++mi) {
                    MMA_F16(acc[mi][np * 2],     afh[mi][0], afh[mi][1], afh[mi][2], afh[mi][3], b0, b1r);
                    MMA_F16(acc[mi][np * 2 + 1], afh[mi][0], afh[mi][1], afh[mi][2], afh[mi][3], b2, b3);
                    MMA_F16(acc[mi][np * 2],     afl[mi][0], afl[mi][1], afl[mi][2], afl[mi][3], b0, b1r);
                    MMA_F16(acc[mi][np * 2 + 1], afl[mi][0], afl[mi][1], afl[mi][2], afl[mi][3], b2, b3);
                }
            }
        }

        if (c < 3) {
            sts_A((c + 1) & 1, rA);
            if (c < 2) ldg_A(c + 2, rA);
        }
    }

    // ---- epilogue: +b1 on cols<128, store fp16 ----
    const int trow  = lane >> 2;
    const int tcol2 = (lane & 3) * 2;
#pragma unroll
    for (int mi = 0; mi < 2; ++mi) {
#pragma unroll
        for (int ni = 0; ni < 16; ++ni) {
            int col = wn * 128 + ni * 8 + tcol2;
            float bx = 0.f, by = 0.f;
            if (col < HH) { bx = __ldg(&b1[col]); by = __ldg(&b1[col + 1]); }
#pragma unroll
            for (int h = 0; h < 2; ++h) {
                int r = row0 + wm * 32 + mi * 16 + trow + h * 8;
                if (r < M) {
                    __half2 v = __floats2half2_rn(acc[mi][ni][h * 2] + bx,
                                                  acc[mi][ni][h * 2 + 1] + by);
                    *reinterpret_cast<__half2*>(UV + (size_t)r * 256 + col) = v;
                }
            }
        }
    }
}

// ---------------- Stage 2: 4 edges per warp, fp16 UV ----------------
__global__ __launch_bounds__(256)
void edge_kernel(const int* __restrict__ eli,
                 const __half* __restrict__ UV,
                 const float* __restrict__ W2,
                 const float* __restrict__ b2,
                 float* __restrict__ out,
                 int E) {
    int gwarp = (blockIdx.x * blockDim.x + threadIdx.x) >> 5;
    int lane  = threadIdx.x & 31;
    int e0 = gwarp * 4;
    if (e0 >= E) return;

    float4 w = __ldg(reinterpret_cast<const float4*>(W2) + lane);

    int s[4], d[4];
#pragma unroll
    for (int i = 0; i < 4; ++i) {
        int e = min(e0 + i, E - 1);
        s[i] = __ldg(&eli[e]);
        d[i] = __ldg(&eli[(size_t)E + e]);
    }
    uint2 ur[4], vr[4];
#pragma unroll
    for (int i = 0; i < 4; ++i) {
        ur[i] = __ldg(reinterpret_cast<const uint2*>(UV + (size_t)s[i] * 256) + lane);
        vr[i] = __ldg(reinterpret_cast<const uint2*>(UV + (size_t)d[i] * 256 + HH) + lane);
    }
    float p[4];
#pragma unroll
    for (int i = 0; i < 4; ++i) {
        const __half2* uh = reinterpret_cast<const __half2*>(&ur[i]);
        const __half2* vh = reinterpret_cast<const __half2*>(&vr[i]);
        float2 u01 = __half22float2(uh[0]);
        float2 u23 = __half22float2(uh[1]);
        float2 v01 = __half22float2(vh[0]);
        float2 v23 = __half22float2(vh[1]);
        p[i] = fmaxf(u01.x + v01.x, 0.f) * w.x + fmaxf(u01.y + v01.y, 0.f) * w.y
             + fmaxf(u23.x + v23.x, 0.f) * w.z + fmaxf(u23.y + v23.y, 0.f) * w.w;
    }
#pragma unroll
    for (int o = 16; o > 0; o >>= 1) {
#pragma unroll
        for (int i = 0; i < 4; ++i)
            p[i] += __shfl_down_sync(0xffffffffu, p[i], o);
    }
    if (lane == 0) {
        float bb = __ldg(b2);
#pragma unroll
        for (int i = 0; i < 4; ++i)
            if (e0 + i < E) out[e0 + i] = p[i] + bb;
    }
}

extern "C" void kernel_launch(void* const* d_in, const int* in_sizes, int n_in,
                              void* d_out, int out_size) {
    const float* z   = (const float*)d_in[0];
    const int*   eli = (const int*)d_in[1];
    const float* W1  = (const float*)d_in[2];
    const float* b1  = (const float*)d_in[3];
    const float* W2  = (const float*)d_in[4];
    const float* b2  = (const float*)d_in[5];
    float*       out = (float*)d_out;

    const int M = in_sizes[0] / DD;
    const int E = out_size;

    __half *UV, *WT;
    cudaGetSymbolAddress((void**)&UV, g_UV);
    cudaGetSymbolAddress((void**)&WT, g_WT);

    cudaFuncSetAttribute(uv_gemm_fused_kernel,
                         cudaFuncAttributeMaxDynamicSharedMemorySize, GSM_TOTAL);

    split_w_kernel<<<(256 * 256 + 255) / 256, 256>>>(W1, WT);

    int gblocks = (M + 127) / 128;
    uv_gemm_fused_kernel<<<gblocks, 256, GSM_TOTAL>>>(z, WT, b1, UV, M);

    int quads = (E + 3) / 4;
    int warpsPerBlock = 256 / 32;
    int nblk = (quads + warpsPerBlock - 1) / warpsPerBlock;
    edge_kernel<<<nblk, 256>>>(eli, UV, W2, b2, out, E);
}

// round 9
// speedup vs baseline: 3.8806x; 1.2125x over previous
#include <cuda_runtime.h>
#include <cuda_bf16.h>
#include <cuda_fp16.h>
#include <cstdint>

// LinkPredictorGAT: N_NODES=100000, D=256, E=1000000, H=128
// out_e = relu(z[src]@W1[:256] + z[dst]@W1[256:] + b1) @ W2 + b2
//
// Stage 0: W1 -> WT fp16, transposed to [N=256,K=256] K-major.
// Stage 1: fp16 HMMA GEMM (single term): LDG Z fp32 -> cvt fp16 -> STS (dbl-buf);
//          cp.async WT (dbl-buf). UV[M,256](fp16) = Z16@W16 (+b1 on cols<128).
// Stage 2: 4 edges/warp on fp16 UV: out = relu(u[src]+v[dst]) . W2 + b2

#define MAX_NODES 100000
#define DD 256
#define HH 128

__device__ __half g_UV[(size_t)MAX_NODES * 2 * HH];     // 51.2 MB
__device__ __half g_WT[256 * 256];                      // 128 KB

__device__ __forceinline__ uint32_t smem_u32(const void* p) {
    uint32_t a;
    asm("{ .reg .u64 t; cvta.to.shared.u64 t, %1; cvt.u32.u64 %0, t; }" : "=r"(a) : "l"(p));
    return a;
}

#define CP_ASYNC16(dst, src) \
    asm volatile("cp.async.cg.shared.global [%0], [%1], 16;" :: "r"(dst), "l"(src) : "memory")
#define CP_COMMIT() asm volatile("cp.async.commit_group;" ::: "memory")
#define CP_WAIT_0() asm volatile("cp.async.wait_group 0;" ::: "memory")

#define LDMATRIX_X4(r0, r1, r2, r3, addr) \
    asm volatile("ldmatrix.sync.aligned.m8n8.x4.shared.b16 {%0,%1,%2,%3}, [%4];" \
                 : "=r"(r0), "=r"(r1), "=r"(r2), "=r"(r3) : "r"(addr))

#define MMA_F16(d, a0, a1, a2, a3, b0, b1) \
    asm volatile("mma.sync.aligned.m16n8k16.row.col.f32.f16.f16.f32 " \
                 "{%0,%1,%2,%3}, {%4,%5,%6,%7}, {%8,%9}, {%0,%1,%2,%3};" \
                 : "+f"((d)[0]), "+f"((d)[1]), "+f"((d)[2]), "+f"((d)[3]) \
                 : "r"(a0), "r"(a1), "r"(a2), "r"(a3), "r"(b0), "r"(b1))

// ---------------- Stage 0: build transposed fp16 W ----------------
__global__ __launch_bounds__(256)
void split_w_kernel(const float* __restrict__ W1, __half* __restrict__ WT) {
    int idx = blockIdx.x * blockDim.x + threadIdx.x;
    if (idx >= 256 * 256) return;
    int n = idx & 255;
    int k = idx >> 8;
    float val = (n < HH) ? W1[(size_t)k * HH + n]
                         : W1[(size_t)(256 + k) * HH + (n - HH)];
    WT[(size_t)n * 256 + k] = __float2half_rn(val);
}

// ---------------- Stage 1: fp16 HMMA GEMM ----------------
// SMEM (96 KB), stages s in {0,1}:
//   A(s) @ s*16384                 [0, 32K)
//   B(s) @ 32768 + s*32768         [32K, 96K)
#define A_OFF(s)  ((s) * 16384)
#define B_OFF(s)  (32768 + (s) * 32768)
#define GSM_TOTAL 98304

__global__ __launch_bounds__(256, 1)
void uv_gemm_fused_kernel(const float* __restrict__ Z,
                          const __half* __restrict__ WT,
                          const float* __restrict__ b1,
                          __half* __restrict__ UV,
                          int M) {
    extern __shared__ char smem[];
    const uint32_t sbase = smem_u32(smem);
    const int tid  = threadIdx.x;
    const int wid  = tid >> 5;
    const int lane = tid & 31;
    const int wm   = wid & 3;          // 4 warp-row groups: 32 rows each
    const int wn   = wid >> 2;         // 2 warp-col groups: 128 cols each
    const int row0 = blockIdx.x * 128;

    const int g  = lane >> 3;
    const int lr = lane & 7;
    const int uAbit = g >> 1;
    const int uBbit = g & 1;
    const int rA0 = wm * 32 + (g & 1) * 8 + lr;
    const int nB0 = wn * 128 + (g >> 1) * 8 + lr;

    float acc[2][16][4];
#pragma unroll
    for (int mi = 0; mi < 2; mi++)
#pragma unroll
        for (int ni = 0; ni < 16; ni++)
#pragma unroll
            for (int q = 0; q < 4; q++) acc[mi][ni][q] = 0.f;

    auto ldg_A = [&](int c, float4 (&rA)[8]) {
        const int kc = c * 64;
#pragma unroll
        for (int i = 0; i < 8; ++i) {
            int idx = tid + i * 256;
            int r = idx >> 4;
            int q = idx & 15;
            int gr = row0 + r; if (gr > M - 1) gr = M - 1;
            rA[i] = __ldg(reinterpret_cast<const float4*>(Z + (size_t)gr * 256 + kc + q * 4));
        }
    };
    auto sts_A = [&](int s, const float4 (&rA)[8]) {
#pragma unroll
        for (int i = 0; i < 8; ++i) {
            int idx = tid + i * 256;
            int r = idx >> 4;
            int q = idx & 15;
            float4 f = rA[i];
            __half2 h01 = __floats2half2_rn(f.x, f.y);
            __half2 h23 = __floats2half2_rn(f.z, f.w);
            uint2 hv = make_uint2(*reinterpret_cast<uint32_t*>(&h01),
                                  *reinterpret_cast<uint32_t*>(&h23));
            uint32_t soff = (uint32_t)(r * 128 + (((q >> 1) ^ (r & 7)) << 4) + (q & 1) * 8);
            *reinterpret_cast<uint2*>(smem + A_OFF(s) + soff) = hv;
        }
    };
    auto issue_B = [&](int c) {
        const int kc = c * 64;
        const int s  = c & 1;
#pragma unroll
        for (int i = 0; i < 8; ++i) {
            int idx = tid + i * 256;
            int n = idx >> 3;
            int u = idx & 7;
            uint32_t soff = (uint32_t)(n * 128 + ((u ^ (n & 7)) << 4));
            CP_ASYNC16(sbase + B_OFF(s) + soff, WT + (size_t)n * 256 + kc + u * 8);
        }
        CP_COMMIT();
    };

    // ---- prologue ----
    float4 rA[8];
    ldg_A(0, rA);
    issue_B(0);
    sts_A(0, rA);
    ldg_A(1, rA);

    for (int c = 0; c < 4; ++c) {
        CP_WAIT_0();
        __syncthreads();

        if (c < 3) issue_B(c + 1);

        const int s = c & 1;
        const uint32_t aBase = sbase + A_OFF(s);
        const uint32_t bBase = sbase + B_OFF(s);

#pragma unroll
        for (int kk = 0; kk < 4; ++kk) {
            uint32_t af[2][4];
#pragma unroll
            for (int mi = 0; mi < 2; ++mi) {
                int r = rA0 + mi * 16;
                uint32_t aoff = (uint32_t)(r * 128 + (((kk * 2 + uAbit) ^ lr) << 4));
                LDMATRIX_X4(af[mi][0], af[mi][1], af[mi][2], af[mi][3], aBase + aoff);
            }
#pragma unroll
            for (int np = 0; np < 8; ++np) {
                int n = nB0 + np * 16;
                uint32_t boff = (uint32_t)(n * 128 + (((kk * 2 + uBbit) ^ lr) << 4));
                uint32_t b0, b1r, b2, b3;
                LDMATRIX_X4(b0, b1r, b2, b3, bBase + boff);
#pragma unroll
                for (int mi = 0; mi < 2; ++mi) {
                    MMA_F16(acc[mi][np * 2],     af[mi][0], af[mi][1], af[mi][2], af[mi][3], b0, b1r);
                    MMA_F16(acc[mi][np * 2 + 1], af[mi][0], af[mi][1], af[mi][2], af[mi][3], b2, b3);
                }
            }
        }

        if (c < 3) {
            sts_A((c + 1) & 1, rA);
            if (c < 2) ldg_A(c + 2, rA);
        }
    }

    // ---- epilogue: +b1 on cols<128, store fp16 ----
    const int trow  = lane >> 2;
    const int tcol2 = (lane & 3) * 2;
#pragma unroll
    for (int mi = 0; mi < 2; ++mi) {
#pragma unroll
        for (int ni = 0; ni < 16; ++ni) {
            int col = wn * 128 + ni * 8 + tcol2;
            float bx = 0.f, by = 0.f;
            if (col < HH) { bx = __ldg(&b1[col]); by = __ldg(&b1[col + 1]); }
#pragma unroll
            for (int h = 0; h < 2; ++h) {
                int r = row0 + wm * 32 + mi * 16 + trow + h * 8;
                if (r < M) {
                    __half2 v = __floats2half2_rn(acc[mi][ni][h * 2] + bx,
                                                  acc[mi][ni][h * 2 + 1] + by);
                    *reinterpret_cast<__half2*>(UV + (size_t)r * 256 + col) = v;
                }
            }
        }
    }
}

// ---------------- Stage 2: 4 edges per warp, fp16 UV ----------------
__global__ __launch_bounds__(256)
void edge_kernel(const int* __restrict__ eli,
                 const __half* __restrict__ UV,
                 const float* __restrict__ W2,
                 const float* __restrict__ b2,
                 float* __restrict__ out,
                 int E) {
    int gwarp = (blockIdx.x * blockDim.x + threadIdx.x) >> 5;
    int lane  = threadIdx.x & 31;
    int e0 = gwarp * 4;
    if (e0 >= E) return;

    float4 w = __ldg(reinterpret_cast<const float4*>(W2) + lane);

    int s[4], d[4];
#pragma unroll
    for (int i = 0; i < 4; ++i) {
        int e = min(e0 + i, E - 1);
        s[i] = __ldg(&eli[e]);
        d[i] = __ldg(&eli[(size_t)E + e]);
    }
    uint2 ur[4], vr[4];
#pragma unroll
    for (int i = 0; i < 4; ++i) {
        ur[i] = __ldg(reinterpret_cast<const uint2*>(UV + (size_t)s[i] * 256) + lane);
        vr[i] = __ldg(reinterpret_cast<const uint2*>(UV + (size_t)d[i] * 256 + HH) + lane);
    }
    float p[4];
#pragma unroll
    for (int i = 0; i < 4; ++i) {
        const __half2* uh = reinterpret_cast<const __half2*>(&ur[i]);
        const __half2* vh = reinterpret_cast<const __half2*>(&vr[i]);
        float2 u01 = __half22float2(uh[0]);
        float2 u23 = __half22float2(uh[1]);
        float2 v01 = __half22float2(vh[0]);
        float2 v23 = __half22float2(vh[1]);
        p[i] = fmaxf(u01.x + v01.x, 0.f) * w.x + fmaxf(u01.y + v01.y, 0.f) * w.y
             + fmaxf(u23.x + v23.x, 0.f) * w.z + fmaxf(u23.y + v23.y, 0.f) * w.w;
    }
#pragma unroll
    for (int o = 16; o > 0; o >>= 1) {
#pragma unroll
        for (int i = 0; i < 4; ++i)
            p[i] += __shfl_down_sync(0xffffffffu, p[i], o);
    }
    if (lane == 0) {
        float bb = __ldg(b2);
#pragma unroll
        for (int i = 0; i < 4; ++i)
            if (e0 + i < E) out[e0 + i] = p[i] + bb;
    }
}

extern "C" void kernel_launch(void* const* d_in, const int* in_sizes, int n_in,
                              void* d_out, int out_size) {
    const float* z   = (const float*)d_in[0];
    const int*   eli = (const int*)d_in[1];
    const float* W1  = (const float*)d_in[2];
    const float* b1  = (const float*)d_in[3];
    const float* W2  = (const float*)d_in[4];
    const float* b2  = (const float*)d_in[5];
    float*       out = (float*)d_out;

    const int M = in_sizes[0] / DD;
    const int E = out_size;

    __half *UV, *WT;
    cudaGetSymbolAddress((void**)&UV, g_UV);
    cudaGetSymbolAddress((void**)&WT, g_WT);

    cudaFuncSetAttribute(uv_gemm_fused_kernel,
                         cudaFuncAttributeMaxDynamicSharedMemorySize, GSM_TOTAL);

    split_w_kernel<<<(256 * 256 + 255) / 256, 256>>>(W1, WT);

    int gblocks = (M + 127) / 128;
    uv_gemm_fused_kernel<<<gblocks, 256, GSM_TOTAL>>>(z, WT, b1, UV, M);

    int quads = (E + 3) / 4;
    int warpsPerBlock = 256 / 32;
    int nblk = (quads + warpsPerBlock - 1) / warpsPerBlock;
    edge_kernel<<<nblk, 256>>>(eli, UV, W2, b2, out, E);
}

// round 10
// speedup vs baseline: 3.9257x; 1.0116x over previous
#include <cuda_runtime.h>
#include <cuda_bf16.h>
#include <cuda_fp16.h>
#include <cstdint>

// LinkPredictorGAT: N_NODES=100000, D=256, E=1000000, H=128
// out_e = relu(z[src]@W1[:256] + z[dst]@W1[256:] + b1) @ W2 + b2
//
// Stage 0: W1 -> WT fp16, transposed to [N=256,K=256] K-major.
// Stage 1: fp16 HMMA GEMM, CTA tile 128x128, 2 CTAs/SM:
//          LDG Z fp32 -> cvt fp16 -> STS (dbl-buf); cp.async WT (dbl-buf).
//          UV[M,256](fp16) = Z16@W16 (+b1 on cols<128).
// Stage 2: 4 edges/warp on fp16 UV: out = relu(u[src]+v[dst]) . W2 + b2

#define MAX_NODES 100000
#define DD 256
#define HH 128

__device__ __half g_UV[(size_t)MAX_NODES * 2 * HH];     // 51.2 MB
__device__ __half g_WT[256 * 256];                      // 128 KB

__device__ __forceinline__ uint32_t smem_u32(const void* p) {
    uint32_t a;
    asm("{ .reg .u64 t; cvta.to.shared.u64 t, %1; cvt.u32.u64 %0, t; }" : "=r"(a) : "l"(p));
    return a;
}

#define CP_ASYNC16(dst, src) \
    asm volatile("cp.async.cg.shared.global [%0], [%1], 16;" :: "r"(dst), "l"(src) : "memory")
#define CP_COMMIT() asm volatile("cp.async.commit_group;" ::: "memory")
#define CP_WAIT_0() asm volatile("cp.async.wait_group 0;" ::: "memory")

#define LDMATRIX_X4(r0, r1, r2, r3, addr) \
    asm volatile("ldmatrix.sync.aligned.m8n8.x4.shared.b16 {%0,%1,%2,%3}, [%4];" \
                 : "=r"(r0), "=r"(r1), "=r"(r2), "=r"(r3) : "r"(addr))

#define MMA_F16(d, a0, a1, a2, a3, b0, b1) \
    asm volatile("mma.sync.aligned.m16n8k16.row.col.f32.f16.f16.f32 " \
                 "{%0,%1,%2,%3}, {%4,%5,%6,%7}, {%8,%9}, {%0,%1,%2,%3};" \
                 : "+f"((d)[0]), "+f"((d)[1]), "+f"((d)[2]), "+f"((d)[3]) \
                 : "r"(a0), "r"(a1), "r"(a2), "r"(a3), "r"(b0), "r"(b1))

// ---------------- Stage 0: build transposed fp16 W ----------------
__global__ __launch_bounds__(256)
void split_w_kernel(const float* __restrict__ W1, __half* __restrict__ WT) {
    int idx = blockIdx.x * blockDim.x + threadIdx.x;
    if (idx >= 256 * 256) return;
    int n = idx & 255;
    int k = idx >> 8;
    float val = (n < HH) ? W1[(size_t)k * HH + n]
                         : W1[(size_t)(256 + k) * HH + (n - HH)];
    WT[(size_t)n * 256 + k] = __float2half_rn(val);
}

// ---------------- Stage 1: fp16 HMMA GEMM, 128x128 tile ----------------
// SMEM (64 KB), stages s in {0,1}:
//   A(s) @ s*16384                 [0, 32K)
//   B(s) @ 32768 + s*16384         [32K, 64K)
#define A_OFF(s)  ((s) * 16384)
#define B_OFF(s)  (32768 + (s) * 16384)
#define GSM_TOTAL 65536

__global__ __launch_bounds__(256, 2)
void uv_gemm_fused_kernel(const float* __restrict__ Z,
                          const __half* __restrict__ WT,
                          const float* __restrict__ b1,
                          __half* __restrict__ UV,
                          int M) {
    extern __shared__ char smem[];
    const uint32_t sbase = smem_u32(smem);
    const int tid  = threadIdx.x;
    const int wid  = tid >> 5;
    const int lane = tid & 31;
    const int wm   = wid & 3;          // 4 warp-row groups: 32 rows each
    const int wn   = wid >> 2;         // 2 warp-col groups: 64 cols each
    const int row0 = blockIdx.x * 128;
    const int col0 = blockIdx.y * 128; // N-half of WT

    const int g  = lane >> 3;
    const int lr = lane & 7;
    const int uAbit = g >> 1;
    const int uBbit = g & 1;
    const int rA0 = wm * 32 + (g & 1) * 8 + lr;
    const int nB0 = wn * 64 + (g >> 1) * 8 + lr;   // within 128-row B tile

    float acc[2][8][4];
#pragma unroll
    for (int mi = 0; mi < 2; mi++)
#pragma unroll
        for (int ni = 0; ni < 8; ni++)
#pragma unroll
            for (int q = 0; q < 4; q++) acc[mi][ni][q] = 0.f;

    auto ldg_A = [&](int c, float4 (&rA)[8]) {
        const int kc = c * 64;
#pragma unroll
        for (int i = 0; i < 8; ++i) {
            int idx = tid + i * 256;
            int r = idx >> 4;
            int q = idx & 15;
            int gr = row0 + r; if (gr > M - 1) gr = M - 1;
            rA[i] = __ldg(reinterpret_cast<const float4*>(Z + (size_t)gr * 256 + kc + q * 4));
        }
    };
    auto sts_A = [&](int s, const float4 (&rA)[8]) {
#pragma unroll
        for (int i = 0; i < 8; ++i) {
            int idx = tid + i * 256;
            int r = idx >> 4;
            int q = idx & 15;
            float4 f = rA[i];
            __half2 h01 = __floats2half2_rn(f.x, f.y);
            __half2 h23 = __floats2half2_rn(f.z, f.w);
            uint2 hv = make_uint2(*reinterpret_cast<uint32_t*>(&h01),
                                  *reinterpret_cast<uint32_t*>(&h23));
            uint32_t soff = (uint32_t)(r * 128 + (((q >> 1) ^ (r & 7)) << 4) + (q & 1) * 8);
            *reinterpret_cast<uint2*>(smem + A_OFF(s) + soff) = hv;
        }
    };
    auto issue_B = [&](int c) {
        const int kc = c * 64;
        const int s  = c & 1;
#pragma unroll
        for (int i = 0; i < 4; ++i) {
            int idx = tid + i * 256;
            int n = idx >> 3;                      // 0..127
            int u = idx & 7;
            uint32_t soff = (uint32_t)(n * 128 + ((u ^ (n & 7)) << 4));
            CP_ASYNC16(sbase + B_OFF(s) + soff, WT + (size_t)(col0 + n) * 256 + kc + u * 8);
        }
        CP_COMMIT();
    };

    // ---- prologue ----
    float4 rA[8];
    ldg_A(0, rA);
    issue_B(0);
    sts_A(0, rA);
    ldg_A(1, rA);

    for (int c = 0; c < 4; ++c) {
        CP_WAIT_0();
        __syncthreads();

        if (c < 3) issue_B(c + 1);

        const int s = c & 1;
        const uint32_t aBase = sbase + A_OFF(s);
        const uint32_t bBase = sbase + B_OFF(s);

#pragma unroll
        for (int kk = 0; kk < 4; ++kk) {
            uint32_t af[2][4];
#pragma unroll
            for (int mi = 0; mi < 2; ++mi) {
                int r = rA0 + mi * 16;
                uint32_t aoff = (uint32_t)(r * 128 + (((kk * 2 + uAbit) ^ lr) << 4));
                LDMATRIX_X4(af[mi][0], af[mi][1], af[mi][2], af[mi][3], aBase + aoff);
            }
#pragma unroll
            for (int np = 0; np < 4; ++np) {
                int n = nB0 + np * 16;
                uint32_t boff = (uint32_t)(n * 128 + (((kk * 2 + uBbit) ^ lr) << 4));
                uint32_t b0, b1r, b2, b3;
                LDMATRIX_X4(b0, b1r, b2, b3, bBase + boff);
#pragma unroll
                for (int mi = 0; mi < 2; ++mi) {
                    MMA_F16(acc[mi][np * 2],     af[mi][0], af[mi][1], af[mi][2], af[mi][3], b0, b1r);
                    MMA_F16(acc[mi][np * 2 + 1], af[mi][0], af[mi][1], af[mi][2], af[mi][3], b2, b3);
                }
            }
        }

        if (c < 3) {
            sts_A((c + 1) & 1, rA);
            if (c < 2) ldg_A(c + 2, rA);
        }
    }

    // ---- epilogue: +b1 on cols<128, store fp16 ----
    const int trow  = lane >> 2;
    const int tcol2 = (lane & 3) * 2;
#pragma unroll
    for (int mi = 0; mi < 2; ++mi) {
#pragma unroll
        for (int ni = 0; ni < 8; ++ni) {
            int col = col0 + wn * 64 + ni * 8 + tcol2;
            float bx = 0.f, by = 0.f;
            if (col < HH) { bx = __ldg(&b1[col]); by = __ldg(&b1[col + 1]); }
#pragma unroll
            for (int h = 0; h < 2; ++h) {
                int r = row0 + wm * 32 + mi * 16 + trow + h * 8;
                if (r < M) {
                    __half2 v = __floats2half2_rn(acc[mi][ni][h * 2] + bx,
                                                  acc[mi][ni][h * 2 + 1] + by);
                    *reinterpret_cast<__half2*>(UV + (size_t)r * 256 + col) = v;
                }
            }
        }
    }
}

// ---------------- Stage 2: 4 edges per warp, fp16 UV ----------------
__global__ __launch_bounds__(256)
void edge_kernel(const int* __restrict__ eli,
                 const __half* __restrict__ UV,
                 const float* __restrict__ W2,
                 const float* __restrict__ b2,
                 float* __restrict__ out,
                 int E) {
    int gwarp = (blockIdx.x * blockDim.x + threadIdx.x) >> 5;
    int lane  = threadIdx.x & 31;
    int e0 = gwarp * 4;
    if (e0 >= E) return;

    float4 w = __ldg(reinterpret_cast<const float4*>(W2) + lane);

    int s[4], d[4];
#pragma unroll
    for (int i = 0; i < 4; ++i) {
        int e = min(e0 + i, E - 1);
        s[i] = __ldg(&eli[e]);
        d[i] = __ldg(&eli[(size_t)E + e]);
    }
    uint2 ur[4], vr[4];
#pragma unroll
    for (int i = 0; i < 4; ++i) {
        ur[i] = __ldg(reinterpret_cast<const uint2*>(UV + (size_t)s[i] * 256) + lane);
        vr[i] = __ldg(reinterpret_cast<const uint2*>(UV + (size_t)d[i] * 256 + HH) + lane);
    }
    float p[4];
#pragma unroll
    for (int i = 0; i < 4; ++i) {
        const __half2* uh = reinterpret_cast<const __half2*>(&ur[i]);
        const __half2* vh = reinterpret_cast<const __half2*>(&vr[i]);
        float2 u01 = __half22float2(uh[0]);
        float2 u23 = __half22float2(uh[1]);
        float2 v01 = __half22float2(vh[0]);
        float2 v23 = __half22float2(vh[1]);
        p[i] = fmaxf(u01.x + v01.x, 0.f) * w.x + fmaxf(u01.y + v01.y, 0.f) * w.y
             + fmaxf(u23.x + v23.x, 0.f) * w.z + fmaxf(u23.y + v23.y, 0.f) * w.w;
    }
#pragma unroll
    for (int o = 16; o > 0; o >>= 1) {
#pragma unroll
        for (int i = 0; i < 4; ++i)
            p[i] += __shfl_down_sync(0xffffffffu, p[i], o);
    }
    if (lane == 0) {
        float bb = __ldg(b2);
#pragma unroll
        for (int i = 0; i < 4; ++i)
            if (e0 + i < E) out[e0 + i] = p[i] + bb;
    }
}

extern "C" void kernel_launch(void* const* d_in, const int* in_sizes, int n_in,
                              void* d_out, int out_size) {
    const float* z   = (const float*)d_in[0];
    const int*   eli = (const int*)d_in[1];
    const float* W1  = (const float*)d_in[2];
    const float* b1  = (const float*)d_in[3];
    const float* W2  = (const float*)d_in[4];
    const float* b2  = (const float*)d_in[5];
    float*       out = (float*)d_out;

    const int M = in_sizes[0] / DD;
    const int E = out_size;

    __half *UV, *WT;
    cudaGetSymbolAddress((void**)&UV, g_UV);
    cudaGetSymbolAddress((void**)&WT, g_WT);

    cudaFuncSetAttribute(uv_gemm_fused_kernel,
                         cudaFuncAttributeMaxDynamicSharedMemorySize, GSM_TOTAL);

    split_w_kernel<<<(256 * 256 + 255) / 256, 256>>>(W1, WT);

    dim3 ggrid((M + 127) / 128, 2);
    uv_gemm_fused_kernel<<<ggrid, 256, GSM_TOTAL>>>(z, WT, b1, UV, M);

    int quads = (E + 3) / 4;
    int warpsPerBlock = 256 / 32;
    int nblk = (quads + warpsPerBlock - 1) / warpsPerBlock;
    edge_kernel<<<nblk, 256>>>(eli, UV, W2, b2, out, E);
}